// round 4
// baseline (speedup 1.0000x reference)
#include <cuda_runtime.h>
#include <cstdint>

#define BB 128
#define SSEQ 16
#define TT 256
#define ZZ 512
#define HC 1024
#define EE 512
#define HD 1024
#define VV 1024

// ---------------- scratch (device globals; zero-init at module load) ----------------
__device__ float g_zero[BB * HD];                       // never written: stays zero
__device__ float g_cin[SSEQ * BB * HC];
__device__ float g_gxc[SSEQ * BB * 4 * HC];
__device__ float g_condh[SSEQ * BB * HC];
__device__ float g_emb[SSEQ * BB * EE];
__device__ float g_gxe[SSEQ * BB * 4 * HD];
__device__ float g_gx[TT * BB * 4 * HD];
__device__ float g_h0[TT * BB * HD];
__device__ float g_h1[TT * BB * HD];
__device__ float g_gates[BB * 4 * HD];
__device__ float g_cbuf[BB * HD];
__device__ float g_bsum[3 * 4 * HD];

// grid-barrier state (monotonic generation; count self-resets)
__device__ volatile unsigned int g_bar_gen;
__device__ unsigned int g_bar_cnt;

// ---------------- packed fp32x2 helpers (SASS FFMA2 path) ----------------
__device__ __forceinline__ unsigned long long ffma2(unsigned long long a,
                                                    unsigned long long b,
                                                    unsigned long long c) {
    unsigned long long d;
    asm("fma.rn.f32x2 %0, %1, %2, %3;" : "=l"(d) : "l"(a), "l"(b), "l"(c));
    return d;
}
__device__ __forceinline__ unsigned long long pk2(float x, float y) {
    unsigned long long r;
    asm("mov.b64 %0, {%1, %2};" : "=l"(r) : "f"(x), "f"(y));
    return r;
}
__device__ __forceinline__ float2 upk2(unsigned long long v) {
    float2 d;
    asm("mov.b64 {%0, %1}, %2;" : "=f"(d.x), "=f"(d.y) : "l"(v));
    return d;
}

// ---------------- generic NT GEMM (big, fully parallel projections) ----------------
// amode: 0 = A row m;  1 = z-gather (m = s*BB+b reads z row b*SSEQ+s);
//        2 = prev-x   (m = t*BB+b reads x row b*TT+t-1, zeros at t==0)
// cinmode: 0 = Cin row m; 1 = Cin row (t>>4)*BB+b
// cmode:   0 = C row m;   1 = C row (b*TT+t)
// act:     0 = none;      1 = tanh
__global__ __launch_bounds__(256)
void gemm_nt(const float* __restrict__ A, const float* __restrict__ W,
             const float* __restrict__ bias, const float* __restrict__ Cin,
             float* __restrict__ C,
             int M, int N, int K, int ldw,
             int amode, int cinmode, int cmode, int act)
{
    __shared__ unsigned long long Ad[16][64];
    __shared__ float Ws[16][64];

    const int tid = threadIdx.x;
    const int m0 = blockIdx.y << 6;
    const int n0 = blockIdx.x << 6;

    const int li = tid >> 2;
    const int lk = (tid & 3) << 2;

    const int m = m0 + li;
    const float* arow;
    if (amode == 0) {
        arow = A + (size_t)m * K;
    } else if (amode == 1) {
        int b = m & (BB - 1), s = m >> 7;
        arow = A + ((size_t)b * SSEQ + s) * K;
    } else {
        int t = m >> 7, b = m & (BB - 1);
        arow = (t == 0) ? g_zero : A + ((size_t)b * TT + (t - 1)) * K;
    }
    arow += lk;
    const float* wrow = W + (size_t)(n0 + li) * ldw + lk;

    const int nkt = K >> 4;
    float4 a_reg = *(const float4*)arow;
    float4 w_reg = *(const float4*)wrow;

    const int ty = tid >> 4;
    const int tx = tid & 15;

    unsigned long long acc[4][2];
#pragma unroll
    for (int r = 0; r < 4; ++r) { acc[r][0] = 0ull; acc[r][1] = 0ull; }

    for (int kt = 0; kt < nkt; ++kt) {
        Ad[lk + 0][li] = pk2(a_reg.x, a_reg.x);
        Ad[lk + 1][li] = pk2(a_reg.y, a_reg.y);
        Ad[lk + 2][li] = pk2(a_reg.z, a_reg.z);
        Ad[lk + 3][li] = pk2(a_reg.w, a_reg.w);
        Ws[lk + 0][li] = w_reg.x;
        Ws[lk + 1][li] = w_reg.y;
        Ws[lk + 2][li] = w_reg.z;
        Ws[lk + 3][li] = w_reg.w;
        __syncthreads();
        if (kt + 1 < nkt) {
            a_reg = *(const float4*)(arow + (size_t)(kt + 1) * 16);
            w_reg = *(const float4*)(wrow + (size_t)(kt + 1) * 16);
        }
#pragma unroll
        for (int k = 0; k < 16; ++k) {
            ulonglong2 a01 = *(const ulonglong2*)&Ad[k][(ty << 2)];
            ulonglong2 a23 = *(const ulonglong2*)&Ad[k][(ty << 2) + 2];
            ulonglong2 w01 = *(const ulonglong2*)&Ws[k][(tx << 2)];
            acc[0][0] = ffma2(a01.x, w01.x, acc[0][0]);
            acc[0][1] = ffma2(a01.x, w01.y, acc[0][1]);
            acc[1][0] = ffma2(a01.y, w01.x, acc[1][0]);
            acc[1][1] = ffma2(a01.y, w01.y, acc[1][1]);
            acc[2][0] = ffma2(a23.x, w01.x, acc[2][0]);
            acc[2][1] = ffma2(a23.x, w01.y, acc[2][1]);
            acc[3][0] = ffma2(a23.y, w01.x, acc[3][0]);
            acc[3][1] = ffma2(a23.y, w01.y, acc[3][1]);
        }
        __syncthreads();
    }

#pragma unroll
    for (int r = 0; r < 4; ++r) {
        const int row = m0 + (ty << 2) + r;
        size_t coff;
        if (cmode == 0) {
            coff = (size_t)row * N;
        } else {
            int t = row >> 7, b = row & (BB - 1);
            coff = ((size_t)b * TT + t) * N;
        }
        size_t cinoff = 0;
        if (Cin) {
            int cr = (cinmode == 0) ? row : (((row >> 11) << 7) + (row & (BB - 1)));
            cinoff = (size_t)cr * N;
        }
#pragma unroll
        for (int p = 0; p < 2; ++p) {
            const int col = n0 + (tx << 2) + (p << 1);
            float2 v = upk2(acc[r][p]);
            if (bias) { v.x += bias[col]; v.y += bias[col + 1]; }
            if (Cin)  { float2 ci = *(const float2*)(Cin + cinoff + col); v.x += ci.x; v.y += ci.y; }
            if (act)  { v.x = tanhf(v.x); v.y = tanhf(v.y); }
            *(float2*)(C + coff + col) = v;
        }
    }
}

// ---------------- grid barrier (all NBLK blocks co-resident) ----------------
#define NBLK 128
__device__ __forceinline__ void grid_barrier()
{
    __syncthreads();
    __threadfence();                 // every thread orders its own global stores
    if (threadIdx.x == 0) {
        unsigned int gen = g_bar_gen;
        if (atomicAdd(&g_bar_cnt, 1u) == NBLK - 1u) {
            g_bar_cnt = 0u;
            __threadfence();
            g_bar_gen = gen + 1u;
        } else {
            while (g_bar_gen == gen) { __nanosleep(64); }
        }
    }
    __syncthreads();
}

// ---------------- persistent LSTM recurrence ----------------
// Per step: gates[128,4096] = h_prev[128,1024] @ W[4096,1024]^T + gx[t]
// then fused cell -> c, h_all[t].  NBLK=128 blocks: 2 m-tiles x 64 n-tiles.
__global__ __launch_bounds__(256)
void lstm_recurrence(const float* __restrict__ W, const float* __restrict__ gx,
                     float* __restrict__ h_all, float* __restrict__ cbuf,
                     float* __restrict__ gates, int T)
{
    __shared__ unsigned long long Ad[16][64];
    __shared__ float Ws[16][64];

    const int tid = threadIdx.x;
    const int bx  = blockIdx.x;
    const int m0 = (bx >> 6) << 6;          // 0 or 64
    const int n0 = (bx & 63) << 6;          // 0..4032

    const int li = tid >> 2;
    const int lk = (tid & 3) << 2;
    const int ty = tid >> 4;
    const int tx = tid & 15;

    const float* wrow = W + (size_t)(n0 + li) * 1024 + lk;

    // cell-phase assignment (blocks 0..31): 64 rows x 64 j
    const int cr0 = (bx >> 4) << 6;         // 0 or 64 (valid for bx<32)
    const int cj0 = (bx & 15) << 6;         // 0..960

    for (int t = 0; t < T; ++t) {
        // ---- gate GEMM phase ----
        const float* hbase = (t == 0) ? g_zero : h_all + (size_t)(t - 1) * BB * 1024;
        const float* arow = hbase + (size_t)(m0 + li) * 1024 + lk;

        float4 a_reg = *(const float4*)arow;
        float4 w_reg = *(const float4*)wrow;

        unsigned long long acc[4][2];
#pragma unroll
        for (int r = 0; r < 4; ++r) { acc[r][0] = 0ull; acc[r][1] = 0ull; }

        for (int kt = 0; kt < 64; ++kt) {
            Ad[lk + 0][li] = pk2(a_reg.x, a_reg.x);
            Ad[lk + 1][li] = pk2(a_reg.y, a_reg.y);
            Ad[lk + 2][li] = pk2(a_reg.z, a_reg.z);
            Ad[lk + 3][li] = pk2(a_reg.w, a_reg.w);
            Ws[lk + 0][li] = w_reg.x;
            Ws[lk + 1][li] = w_reg.y;
            Ws[lk + 2][li] = w_reg.z;
            Ws[lk + 3][li] = w_reg.w;
            __syncthreads();
            if (kt + 1 < 64) {
                a_reg = *(const float4*)(arow + (size_t)(kt + 1) * 16);
                w_reg = *(const float4*)(wrow + (size_t)(kt + 1) * 16);
            }
#pragma unroll
            for (int k = 0; k < 16; ++k) {
                ulonglong2 a01 = *(const ulonglong2*)&Ad[k][(ty << 2)];
                ulonglong2 a23 = *(const ulonglong2*)&Ad[k][(ty << 2) + 2];
                ulonglong2 w01 = *(const ulonglong2*)&Ws[k][(tx << 2)];
                acc[0][0] = ffma2(a01.x, w01.x, acc[0][0]);
                acc[0][1] = ffma2(a01.x, w01.y, acc[0][1]);
                acc[1][0] = ffma2(a01.y, w01.x, acc[1][0]);
                acc[1][1] = ffma2(a01.y, w01.y, acc[1][1]);
                acc[2][0] = ffma2(a23.x, w01.x, acc[2][0]);
                acc[2][1] = ffma2(a23.x, w01.y, acc[2][1]);
                acc[3][0] = ffma2(a23.y, w01.x, acc[3][0]);
                acc[3][1] = ffma2(a23.y, w01.y, acc[3][1]);
            }
            __syncthreads();
        }

        // store gate tile (+gx addend) to global scratch
        const float* gxt = gx + (size_t)t * BB * 4096;
#pragma unroll
        for (int r = 0; r < 4; ++r) {
            const int row = m0 + (ty << 2) + r;
#pragma unroll
            for (int p = 0; p < 2; ++p) {
                const int col = n0 + (tx << 2) + (p << 1);
                float2 v = upk2(acc[r][p]);
                float2 gv = *(const float2*)(gxt + (size_t)row * 4096 + col);
                v.x += gv.x; v.y += gv.y;
                *(float2*)(gates + (size_t)row * 4096 + col) = v;
            }
        }

        grid_barrier();

        // ---- cell phase (blocks 0..31) ----
        if (bx < 32) {
#pragma unroll
            for (int it = 0; it < 16; ++it) {
                int idx = (it << 8) + tid;          // 0..4095
                int row = cr0 + (idx >> 6);
                int j   = cj0 + (idx & 63);
                const float* gr = gates + (size_t)row * 4096;
                float gi = __ldcg(gr + j);
                float gf = __ldcg(gr + 1024 + j);
                float gg = __ldcg(gr + 2048 + j);
                float go = __ldcg(gr + 3072 + j);
                float i = 1.f / (1.f + expf(-gi));
                float f = 1.f / (1.f + expf(-gf));
                float o = 1.f / (1.f + expf(-go));
                float cprev = (t == 0) ? 0.f : cbuf[(size_t)row * 1024 + j];
                float c = f * cprev + i * tanhf(gg);
                cbuf[(size_t)row * 1024 + j] = c;
                h_all[(size_t)t * BB * 1024 + (size_t)row * 1024 + j] = o * tanhf(c);
            }
        }

        grid_barrier();
    }
}

__global__ void add2(const float* __restrict__ a, const float* __restrict__ b,
                     float* __restrict__ o, int n)
{
    int i = blockIdx.x * blockDim.x + threadIdx.x;
    if (i < n) o[i] = a[i] + b[i];
}

// ---------------- host ----------------
extern "C" void kernel_launch(void* const* d_in, const int* in_sizes, int n_in,
                              void* d_out, int out_size)
{
    const float* z      = (const float*)d_in[0];
    const float* x      = (const float*)d_in[1];
    const float* fcz_w  = (const float*)d_in[2];
    const float* fcz_b  = (const float*)d_in[3];
    const float* c_wih  = (const float*)d_in[4];
    const float* c_whh  = (const float*)d_in[5];
    const float* c_bih  = (const float*)d_in[6];
    const float* c_bhh  = (const float*)d_in[7];
    const float* fcc_w  = (const float*)d_in[8];
    const float* fcc_b  = (const float*)d_in[9];
    const float* d0_wih = (const float*)d_in[10];
    const float* d0_whh = (const float*)d_in[11];
    const float* d0_bih = (const float*)d_in[12];
    const float* d0_bhh = (const float*)d_in[13];
    const float* d1_wih = (const float*)d_in[14];
    const float* d1_whh = (const float*)d_in[15];
    const float* d1_bih = (const float*)d_in[16];
    const float* d1_bhh = (const float*)d_in[17];
    const float* out_w  = (const float*)d_in[18];
    const float* out_b  = (const float*)d_in[19];
    float* out = (float*)d_out;

    float *cin, *gxc, *condh, *emb, *gxe, *gx, *h0, *h1, *gates, *cbuf, *bsum;
    cudaGetSymbolAddress((void**)&cin,   g_cin);
    cudaGetSymbolAddress((void**)&gxc,   g_gxc);
    cudaGetSymbolAddress((void**)&condh, g_condh);
    cudaGetSymbolAddress((void**)&emb,   g_emb);
    cudaGetSymbolAddress((void**)&gxe,   g_gxe);
    cudaGetSymbolAddress((void**)&gx,    g_gx);
    cudaGetSymbolAddress((void**)&h0,    g_h0);
    cudaGetSymbolAddress((void**)&h1,    g_h1);
    cudaGetSymbolAddress((void**)&gates, g_gates);
    cudaGetSymbolAddress((void**)&cbuf,  g_cbuf);
    cudaGetSymbolAddress((void**)&bsum,  g_bsum);

    dim3 blk(256);

    // combined biases: [0..4095] conductor, [4096..8191] dec0, [8192..12287] dec1
    add2<<<16, 256>>>(c_bih,  c_bhh,  bsum,        4096);
    add2<<<16, 256>>>(d0_bih, d0_bhh, bsum + 4096, 4096);
    add2<<<16, 256>>>(d1_bih, d1_bhh, bsum + 8192, 4096);

    // ---- conductor ----
    gemm_nt<<<dim3(HC / 64, (SSEQ * BB) / 64), blk>>>(
        z, fcz_w, fcz_b, nullptr, cin, SSEQ * BB, HC, ZZ, ZZ, 1, 0, 0, 0);
    gemm_nt<<<dim3(4 * HC / 64, (SSEQ * BB) / 64), blk>>>(
        cin, c_wih, bsum, nullptr, gxc, SSEQ * BB, 4 * HC, HC, HC, 0, 0, 0, 0);
    lstm_recurrence<<<NBLK, blk>>>(c_whh, gxc, condh, cbuf, gates, SSEQ);
    gemm_nt<<<dim3(EE / 64, (SSEQ * BB) / 64), blk>>>(
        condh, fcc_w, fcc_b, nullptr, emb, SSEQ * BB, EE, HC, HC, 0, 0, 0, 1);
    gemm_nt<<<dim3(4 * HD / 64, (SSEQ * BB) / 64), blk>>>(
        emb, d0_wih + VV, bsum + 4096, nullptr, gxe,
        SSEQ * BB, 4 * HD, EE, VV + EE, 0, 0, 0, 0);

    // ---- decoder layer 0 ----
    gemm_nt<<<dim3(4 * HD / 64, (TT * BB) / 64), blk>>>(
        x, d0_wih, nullptr, gxe, gx, TT * BB, 4 * HD, VV, VV + EE, 2, 1, 0, 0);
    lstm_recurrence<<<NBLK, blk>>>(d0_whh, gx, h0, cbuf, gates, TT);

    // ---- decoder layer 1 ----
    gemm_nt<<<dim3(4 * HD / 64, (TT * BB) / 64), blk>>>(
        h0, d1_wih, bsum + 8192, nullptr, gx, TT * BB, 4 * HD, HD, HD, 0, 0, 0, 0);
    lstm_recurrence<<<NBLK, blk>>>(d1_whh, gx, h1, cbuf, gates, TT);

    // ---- output projection (time-major -> [B,T,V]) ----
    gemm_nt<<<dim3(VV / 64, (TT * BB) / 64), blk>>>(
        h1, out_w, out_b, nullptr, out, TT * BB, VV, HD, HD, 0, 0, 1, 0);
}

// round 5
// speedup vs baseline: 1.0013x; 1.0013x over previous
#include <cuda_runtime.h>
#include <cstdint>

#define BB 128
#define SSEQ 16
#define TT 256
#define ZZ 512
#define HC 1024
#define EE 512
#define HD 1024
#define VV 1024

// ---------------- scratch (device globals; zero-init at module load) ----------------
__device__ float g_zero[BB * HD];                       // never written: stays zero
__device__ float g_cin[SSEQ * BB * HC];
__device__ float g_gxc[SSEQ * BB * 4 * HC];
__device__ float g_condh[SSEQ * BB * HC];
__device__ float g_emb[SSEQ * BB * EE];
__device__ float g_gxe[SSEQ * BB * 4 * HD];
__device__ float g_gx[TT * BB * 4 * HD];
__device__ float g_h0[TT * BB * HD];
__device__ float g_h1[TT * BB * HD];
__device__ float g_gates[BB * 4 * HD];
__device__ float g_cbuf[BB * HD];
__device__ float g_bsum[3 * 4 * HD];

// grid-barrier state (monotonic generation; count self-resets)
__device__ volatile unsigned int g_bar_gen;
__device__ unsigned int g_bar_cnt;

// ---------------- packed fp32x2 helpers (SASS FFMA2 path) ----------------
__device__ __forceinline__ unsigned long long ffma2(unsigned long long a,
                                                    unsigned long long b,
                                                    unsigned long long c) {
    unsigned long long d;
    asm("fma.rn.f32x2 %0, %1, %2, %3;" : "=l"(d) : "l"(a), "l"(b), "l"(c));
    return d;
}
__device__ __forceinline__ unsigned long long pk2(float x, float y) {
    unsigned long long r;
    asm("mov.b64 %0, {%1, %2};" : "=l"(r) : "f"(x), "f"(y));
    return r;
}
__device__ __forceinline__ float2 upk2(unsigned long long v) {
    float2 d;
    asm("mov.b64 {%0, %1}, %2;" : "=f"(d.x), "=f"(d.y) : "l"(v));
    return d;
}

// ---------------- generic NT GEMM (big, fully parallel projections) ----------------
// amode: 0 = A row m;  1 = z-gather (m = s*BB+b reads z row b*SSEQ+s);
//        2 = prev-x   (m = t*BB+b reads x row b*TT+t-1, zeros at t==0)
// cinmode: 0 = Cin row m; 1 = Cin row (t>>4)*BB+b
// cmode:   0 = C row m;   1 = C row (b*TT+t)
// act:     0 = none;      1 = tanh
__global__ __launch_bounds__(256)
void gemm_nt(const float* __restrict__ A, const float* __restrict__ W,
             const float* __restrict__ bias, const float* __restrict__ Cin,
             float* __restrict__ C,
             int M, int N, int K, int ldw,
             int amode, int cinmode, int cmode, int act)
{
    __shared__ unsigned long long Ad[16][64];
    __shared__ float Ws[16][64];

    const int tid = threadIdx.x;
    const int m0 = blockIdx.y << 6;
    const int n0 = blockIdx.x << 6;

    const int li = tid >> 2;
    const int lk = (tid & 3) << 2;

    const int m = m0 + li;
    const float* arow;
    if (amode == 0) {
        arow = A + (size_t)m * K;
    } else if (amode == 1) {
        int b = m & (BB - 1), s = m >> 7;
        arow = A + ((size_t)b * SSEQ + s) * K;
    } else {
        int t = m >> 7, b = m & (BB - 1);
        arow = (t == 0) ? g_zero : A + ((size_t)b * TT + (t - 1)) * K;
    }
    arow += lk;
    const float* wrow = W + (size_t)(n0 + li) * ldw + lk;

    const int nkt = K >> 4;
    float4 a_reg = *(const float4*)arow;
    float4 w_reg = *(const float4*)wrow;

    const int ty = tid >> 4;
    const int tx = tid & 15;

    unsigned long long acc[4][2];
#pragma unroll
    for (int r = 0; r < 4; ++r) { acc[r][0] = 0ull; acc[r][1] = 0ull; }

    for (int kt = 0; kt < nkt; ++kt) {
        Ad[lk + 0][li] = pk2(a_reg.x, a_reg.x);
        Ad[lk + 1][li] = pk2(a_reg.y, a_reg.y);
        Ad[lk + 2][li] = pk2(a_reg.z, a_reg.z);
        Ad[lk + 3][li] = pk2(a_reg.w, a_reg.w);
        Ws[lk + 0][li] = w_reg.x;
        Ws[lk + 1][li] = w_reg.y;
        Ws[lk + 2][li] = w_reg.z;
        Ws[lk + 3][li] = w_reg.w;
        __syncthreads();
        if (kt + 1 < nkt) {
            a_reg = *(const float4*)(arow + (size_t)(kt + 1) * 16);
            w_reg = *(const float4*)(wrow + (size_t)(kt + 1) * 16);
        }
#pragma unroll
        for (int k = 0; k < 16; ++k) {
            ulonglong2 a01 = *(const ulonglong2*)&Ad[k][(ty << 2)];
            ulonglong2 a23 = *(const ulonglong2*)&Ad[k][(ty << 2) + 2];
            ulonglong2 w01 = *(const ulonglong2*)&Ws[k][(tx << 2)];
            acc[0][0] = ffma2(a01.x, w01.x, acc[0][0]);
            acc[0][1] = ffma2(a01.x, w01.y, acc[0][1]);
            acc[1][0] = ffma2(a01.y, w01.x, acc[1][0]);
            acc[1][1] = ffma2(a01.y, w01.y, acc[1][1]);
            acc[2][0] = ffma2(a23.x, w01.x, acc[2][0]);
            acc[2][1] = ffma2(a23.x, w01.y, acc[2][1]);
            acc[3][0] = ffma2(a23.y, w01.x, acc[3][0]);
            acc[3][1] = ffma2(a23.y, w01.y, acc[3][1]);
        }
        __syncthreads();
    }

#pragma unroll
    for (int r = 0; r < 4; ++r) {
        const int row = m0 + (ty << 2) + r;
        size_t coff;
        if (cmode == 0) {
            coff = (size_t)row * N;
        } else {
            int t = row >> 7, b = row & (BB - 1);
            coff = ((size_t)b * TT + t) * N;
        }
        size_t cinoff = 0;
        if (Cin) {
            int cr = (cinmode == 0) ? row : (((row >> 11) << 7) + (row & (BB - 1)));
            cinoff = (size_t)cr * N;
        }
#pragma unroll
        for (int p = 0; p < 2; ++p) {
            const int col = n0 + (tx << 2) + (p << 1);
            float2 v = upk2(acc[r][p]);
            if (bias) { v.x += bias[col]; v.y += bias[col + 1]; }
            if (Cin)  { float2 ci = *(const float2*)(Cin + cinoff + col); v.x += ci.x; v.y += ci.y; }
            if (act)  { v.x = tanhf(v.x); v.y = tanhf(v.y); }
            *(float2*)(C + coff + col) = v;
        }
    }
}

// ---------------- grid barrier (all NBLK blocks co-resident) ----------------
#define NBLK 128
__device__ __forceinline__ void grid_barrier()
{
    __syncthreads();
    __threadfence();                 // every thread orders its own global stores
    if (threadIdx.x == 0) {
        unsigned int gen = g_bar_gen;
        if (atomicAdd(&g_bar_cnt, 1u) == NBLK - 1u) {
            g_bar_cnt = 0u;
            __threadfence();
            g_bar_gen = gen + 1u;
        } else {
            while (g_bar_gen == gen) { __nanosleep(64); }
        }
    }
    __syncthreads();
}

// ---------------- persistent LSTM recurrence ----------------
// Per step: gates[128,4096] = h_prev[128,1024] @ W[4096,1024]^T + gx[t]
// then fused cell -> c, h_all[t].  NBLK=128 blocks: 2 m-tiles x 64 n-tiles.
__global__ __launch_bounds__(256)
void lstm_recurrence(const float* __restrict__ W, const float* __restrict__ gx,
                     float* __restrict__ h_all, float* __restrict__ cbuf,
                     float* __restrict__ gates, int T)
{
    __shared__ unsigned long long Ad[16][64];
    __shared__ float Ws[16][64];

    const int tid = threadIdx.x;
    const int bx  = blockIdx.x;
    const int m0 = (bx >> 6) << 6;          // 0 or 64
    const int n0 = (bx & 63) << 6;          // 0..4032

    const int li = tid >> 2;
    const int lk = (tid & 3) << 2;
    const int ty = tid >> 4;
    const int tx = tid & 15;

    const float* wrow = W + (size_t)(n0 + li) * 1024 + lk;

    // cell-phase assignment (blocks 0..31): 64 rows x 64 j
    const int cr0 = (bx >> 4) << 6;         // 0 or 64 (valid for bx<32)
    const int cj0 = (bx & 15) << 6;         // 0..960

    for (int t = 0; t < T; ++t) {
        // ---- gate GEMM phase ----
        const float* hbase = (t == 0) ? g_zero : h_all + (size_t)(t - 1) * BB * 1024;
        const float* arow = hbase + (size_t)(m0 + li) * 1024 + lk;

        float4 a_reg = *(const float4*)arow;
        float4 w_reg = *(const float4*)wrow;

        unsigned long long acc[4][2];
#pragma unroll
        for (int r = 0; r < 4; ++r) { acc[r][0] = 0ull; acc[r][1] = 0ull; }

        for (int kt = 0; kt < 64; ++kt) {
            Ad[lk + 0][li] = pk2(a_reg.x, a_reg.x);
            Ad[lk + 1][li] = pk2(a_reg.y, a_reg.y);
            Ad[lk + 2][li] = pk2(a_reg.z, a_reg.z);
            Ad[lk + 3][li] = pk2(a_reg.w, a_reg.w);
            Ws[lk + 0][li] = w_reg.x;
            Ws[lk + 1][li] = w_reg.y;
            Ws[lk + 2][li] = w_reg.z;
            Ws[lk + 3][li] = w_reg.w;
            __syncthreads();
            if (kt + 1 < 64) {
                a_reg = *(const float4*)(arow + (size_t)(kt + 1) * 16);
                w_reg = *(const float4*)(wrow + (size_t)(kt + 1) * 16);
            }
#pragma unroll
            for (int k = 0; k < 16; ++k) {
                ulonglong2 a01 = *(const ulonglong2*)&Ad[k][(ty << 2)];
                ulonglong2 a23 = *(const ulonglong2*)&Ad[k][(ty << 2) + 2];
                ulonglong2 w01 = *(const ulonglong2*)&Ws[k][(tx << 2)];
                acc[0][0] = ffma2(a01.x, w01.x, acc[0][0]);
                acc[0][1] = ffma2(a01.x, w01.y, acc[0][1]);
                acc[1][0] = ffma2(a01.y, w01.x, acc[1][0]);
                acc[1][1] = ffma2(a01.y, w01.y, acc[1][1]);
                acc[2][0] = ffma2(a23.x, w01.x, acc[2][0]);
                acc[2][1] = ffma2(a23.x, w01.y, acc[2][1]);
                acc[3][0] = ffma2(a23.y, w01.x, acc[3][0]);
                acc[3][1] = ffma2(a23.y, w01.y, acc[3][1]);
            }
            __syncthreads();
        }

        // store gate tile (+gx addend) to global scratch
        const float* gxt = gx + (size_t)t * BB * 4096;
#pragma unroll
        for (int r = 0; r < 4; ++r) {
            const int row = m0 + (ty << 2) + r;
#pragma unroll
            for (int p = 0; p < 2; ++p) {
                const int col = n0 + (tx << 2) + (p << 1);
                float2 v = upk2(acc[r][p]);
                float2 gv = *(const float2*)(gxt + (size_t)row * 4096 + col);
                v.x += gv.x; v.y += gv.y;
                *(float2*)(gates + (size_t)row * 4096 + col) = v;
            }
        }

        grid_barrier();

        // ---- cell phase (blocks 0..31) ----
        if (bx < 32) {
#pragma unroll
            for (int it = 0; it < 16; ++it) {
                int idx = (it << 8) + tid;          // 0..4095
                int row = cr0 + (idx >> 6);
                int j   = cj0 + (idx & 63);
                const float* gr = gates + (size_t)row * 4096;
                float gi = __ldcg(gr + j);
                float gf = __ldcg(gr + 1024 + j);
                float gg = __ldcg(gr + 2048 + j);
                float go = __ldcg(gr + 3072 + j);
                float i = 1.f / (1.f + expf(-gi));
                float f = 1.f / (1.f + expf(-gf));
                float o = 1.f / (1.f + expf(-go));
                float cprev = (t == 0) ? 0.f : cbuf[(size_t)row * 1024 + j];
                float c = f * cprev + i * tanhf(gg);
                cbuf[(size_t)row * 1024 + j] = c;
                h_all[(size_t)t * BB * 1024 + (size_t)row * 1024 + j] = o * tanhf(c);
            }
        }

        grid_barrier();
    }
}

__global__ void add2(const float* __restrict__ a, const float* __restrict__ b,
                     float* __restrict__ o, int n)
{
    int i = blockIdx.x * blockDim.x + threadIdx.x;
    if (i < n) o[i] = a[i] + b[i];
}

// ---------------- host ----------------
extern "C" void kernel_launch(void* const* d_in, const int* in_sizes, int n_in,
                              void* d_out, int out_size)
{
    const float* z      = (const float*)d_in[0];
    const float* x      = (const float*)d_in[1];
    const float* fcz_w  = (const float*)d_in[2];
    const float* fcz_b  = (const float*)d_in[3];
    const float* c_wih  = (const float*)d_in[4];
    const float* c_whh  = (const float*)d_in[5];
    const float* c_bih  = (const float*)d_in[6];
    const float* c_bhh  = (const float*)d_in[7];
    const float* fcc_w  = (const float*)d_in[8];
    const float* fcc_b  = (const float*)d_in[9];
    const float* d0_wih = (const float*)d_in[10];
    const float* d0_whh = (const float*)d_in[11];
    const float* d0_bih = (const float*)d_in[12];
    const float* d0_bhh = (const float*)d_in[13];
    const float* d1_wih = (const float*)d_in[14];
    const float* d1_whh = (const float*)d_in[15];
    const float* d1_bih = (const float*)d_in[16];
    const float* d1_bhh = (const float*)d_in[17];
    const float* out_w  = (const float*)d_in[18];
    const float* out_b  = (const float*)d_in[19];
    float* out = (float*)d_out;

    float *cin, *gxc, *condh, *emb, *gxe, *gx, *h0, *h1, *gates, *cbuf, *bsum;
    cudaGetSymbolAddress((void**)&cin,   g_cin);
    cudaGetSymbolAddress((void**)&gxc,   g_gxc);
    cudaGetSymbolAddress((void**)&condh, g_condh);
    cudaGetSymbolAddress((void**)&emb,   g_emb);
    cudaGetSymbolAddress((void**)&gxe,   g_gxe);
    cudaGetSymbolAddress((void**)&gx,    g_gx);
    cudaGetSymbolAddress((void**)&h0,    g_h0);
    cudaGetSymbolAddress((void**)&h1,    g_h1);
    cudaGetSymbolAddress((void**)&gates, g_gates);
    cudaGetSymbolAddress((void**)&cbuf,  g_cbuf);
    cudaGetSymbolAddress((void**)&bsum,  g_bsum);

    dim3 blk(256);

    // combined biases: [0..4095] conductor, [4096..8191] dec0, [8192..12287] dec1
    add2<<<16, 256>>>(c_bih,  c_bhh,  bsum,        4096);
    add2<<<16, 256>>>(d0_bih, d0_bhh, bsum + 4096, 4096);
    add2<<<16, 256>>>(d1_bih, d1_bhh, bsum + 8192, 4096);

    // ---- conductor ----
    gemm_nt<<<dim3(HC / 64, (SSEQ * BB) / 64), blk>>>(
        z, fcz_w, fcz_b, nullptr, cin, SSEQ * BB, HC, ZZ, ZZ, 1, 0, 0, 0);
    gemm_nt<<<dim3(4 * HC / 64, (SSEQ * BB) / 64), blk>>>(
        cin, c_wih, bsum, nullptr, gxc, SSEQ * BB, 4 * HC, HC, HC, 0, 0, 0, 0);
    lstm_recurrence<<<NBLK, blk>>>(c_whh, gxc, condh, cbuf, gates, SSEQ);
    gemm_nt<<<dim3(EE / 64, (SSEQ * BB) / 64), blk>>>(
        condh, fcc_w, fcc_b, nullptr, emb, SSEQ * BB, EE, HC, HC, 0, 0, 0, 1);
    gemm_nt<<<dim3(4 * HD / 64, (SSEQ * BB) / 64), blk>>>(
        emb, d0_wih + VV, bsum + 4096, nullptr, gxe,
        SSEQ * BB, 4 * HD, EE, VV + EE, 0, 0, 0, 0);

    // ---- decoder layer 0 ----
    gemm_nt<<<dim3(4 * HD / 64, (TT * BB) / 64), blk>>>(
        x, d0_wih, nullptr, gxe, gx, TT * BB, 4 * HD, VV, VV + EE, 2, 1, 0, 0);
    lstm_recurrence<<<NBLK, blk>>>(d0_whh, gx, h0, cbuf, gates, TT);

    // ---- decoder layer 1 ----
    gemm_nt<<<dim3(4 * HD / 64, (TT * BB) / 64), blk>>>(
        h0, d1_wih, bsum + 8192, nullptr, gx, TT * BB, 4 * HD, HD, HD, 0, 0, 0, 0);
    lstm_recurrence<<<NBLK, blk>>>(d1_whh, gx, h1, cbuf, gates, TT);

    // ---- output projection (time-major -> [B,T,V]) ----
    gemm_nt<<<dim3(VV / 64, (TT * BB) / 64), blk>>>(
        h1, out_w, out_b, nullptr, out, TT * BB, VV, HD, HD, 0, 0, 1, 0);
}

// round 6
// speedup vs baseline: 1.2298x; 1.2282x over previous
#include <cuda_runtime.h>
#include <cstdint>

#define BB 128
#define SSEQ 16
#define TT 256
#define ZZ 512
#define HC 1024
#define EE 512
#define HD 1024
#define VV 1024
#define NBLK 128

// ---------------- scratch (device globals; zero-init at module load) ----------------
__device__ float g_zero[BB * HD];                       // never written: stays zero
__device__ float g_cin[SSEQ * BB * HC];
__device__ float g_gxc[SSEQ * BB * 4 * HC];             // perm gate order
__device__ float g_condh[SSEQ * BB * HC];
__device__ float g_emb[SSEQ * BB * EE];
__device__ float g_gxe[SSEQ * BB * 4 * HD];             // perm
__device__ float g_gx[TT * BB * 4 * HD];                // perm
__device__ float g_h0[TT * BB * HD];
__device__ float g_h1[TT * BB * HD];
// permuted weights / biases
__device__ float g_cwih_p[4 * HC * HC];
__device__ float g_cwhh_p[4 * HC * HC];
__device__ float g_d0wih_p[4 * HD * (VV + EE)];
__device__ float g_d0whh_p[4 * HD * HD];
__device__ float g_d1wih_p[4 * HD * HD];
__device__ float g_d1whh_p[4 * HD * HD];
__device__ float g_bsum_p[3 * 4 * HD];

// grid-barrier state (monotonic generation; count self-resets)
__device__ volatile unsigned int g_bar_gen;
__device__ unsigned int g_bar_cnt;

// ---------------- packed fp32x2 helpers (SASS FFMA2 path) ----------------
__device__ __forceinline__ unsigned long long ffma2(unsigned long long a,
                                                    unsigned long long b,
                                                    unsigned long long c) {
    unsigned long long d;
    asm("fma.rn.f32x2 %0, %1, %2, %3;" : "=l"(d) : "l"(a), "l"(b), "l"(c));
    return d;
}
__device__ __forceinline__ unsigned long long pk2(float x, float y) {
    unsigned long long r;
    asm("mov.b64 %0, {%1, %2};" : "=l"(r) : "f"(x), "f"(y));
    return r;
}
__device__ __forceinline__ float2 upk2(unsigned long long v) {
    float2 d;
    asm("mov.b64 {%0, %1}, %2;" : "=f"(d.x), "=f"(d.y) : "l"(v));
    return d;
}
__device__ __forceinline__ float4 ldcg4(const float* p) {
    return __ldcg((const float4*)p);
}
__device__ __forceinline__ float sigm(float x) { return 1.f / (1.f + expf(-x)); }

// shared-tile dims (padded: banks conflict-degree 2 = floor; rows stay 16B-aligned)
#define PA 66
#define PW 68

// store one k-tile of A (duplicated pairs) and W into smem buffer `buf`
#define STORE_TILE(buf)                                            \
    do {                                                           \
        Ad[buf][lk + 0][li] = pk2(a_reg.x, a_reg.x);               \
        Ad[buf][lk + 1][li] = pk2(a_reg.y, a_reg.y);               \
        Ad[buf][lk + 2][li] = pk2(a_reg.z, a_reg.z);               \
        Ad[buf][lk + 3][li] = pk2(a_reg.w, a_reg.w);               \
        Ws[buf][lk + 0][li] = w_reg.x;                             \
        Ws[buf][lk + 1][li] = w_reg.y;                             \
        Ws[buf][lk + 2][li] = w_reg.z;                             \
        Ws[buf][lk + 3][li] = w_reg.w;                             \
    } while (0)

#define COMPUTE_TILE(buf)                                                     \
    do {                                                                      \
        _Pragma("unroll")                                                     \
        for (int k = 0; k < 16; ++k) {                                        \
            ulonglong2 a01 = *(const ulonglong2*)&Ad[buf][k][(ty << 2)];      \
            ulonglong2 a23 = *(const ulonglong2*)&Ad[buf][k][(ty << 2) + 2];  \
            ulonglong2 w01 = *(const ulonglong2*)&Ws[buf][k][(tx << 2)];      \
            acc[0][0] = ffma2(a01.x, w01.x, acc[0][0]);                       \
            acc[0][1] = ffma2(a01.x, w01.y, acc[0][1]);                       \
            acc[1][0] = ffma2(a01.y, w01.x, acc[1][0]);                       \
            acc[1][1] = ffma2(a01.y, w01.y, acc[1][1]);                       \
            acc[2][0] = ffma2(a23.x, w01.x, acc[2][0]);                       \
            acc[2][1] = ffma2(a23.x, w01.y, acc[2][1]);                       \
            acc[3][0] = ffma2(a23.y, w01.x, acc[3][0]);                       \
            acc[3][1] = ffma2(a23.y, w01.y, acc[3][1]);                       \
        }                                                                     \
    } while (0)

// ---------------- generic NT GEMM (double-buffered) ----------------
// amode: 0 = A row m;  1 = z-gather (m = s*BB+b reads z row b*SSEQ+s);
//        2 = prev-x   (m = t*BB+b reads x row b*TT+t-1, zeros at t==0)
// cinmode: 0 = Cin row m; 1 = Cin row (t>>4)*BB+b
// cmode:   0 = C row m;   1 = C row (b*TT+t)
// act:     0 = none;      1 = tanh
__global__ __launch_bounds__(256, 2)
void gemm_nt(const float* __restrict__ A, const float* __restrict__ W,
             const float* __restrict__ bias, const float* __restrict__ Cin,
             float* __restrict__ C,
             int M, int N, int K, int ldw,
             int amode, int cinmode, int cmode, int act)
{
    __shared__ unsigned long long Ad[2][16][PA];
    __shared__ float Ws[2][16][PW];

    const int tid = threadIdx.x;
    const int m0 = blockIdx.y << 6;
    const int n0 = blockIdx.x << 6;

    const int li = tid >> 2;
    const int lk = (tid & 3) << 2;
    const int ty = tid >> 4;
    const int tx = tid & 15;

    const int m = m0 + li;
    const float* arow;
    if (amode == 0) {
        arow = A + (size_t)m * K;
    } else if (amode == 1) {
        int b = m & (BB - 1), s = m >> 7;
        arow = A + ((size_t)b * SSEQ + s) * K;
    } else {
        int t = m >> 7, b = m & (BB - 1);
        arow = (t == 0) ? g_zero : A + ((size_t)b * TT + (t - 1)) * K;
    }
    arow += lk;
    const float* wrow = W + (size_t)(n0 + li) * ldw + lk;

    const int nkt = K >> 4;
    float4 a_reg = ldcg4(arow);
    float4 w_reg = ldcg4(wrow);
    STORE_TILE(0);
    __syncthreads();

    unsigned long long acc[4][2];
#pragma unroll
    for (int r = 0; r < 4; ++r) { acc[r][0] = 0ull; acc[r][1] = 0ull; }

    for (int kt = 0; kt < nkt; ++kt) {
        const int cur = kt & 1;
        if (kt + 1 < nkt) {
            a_reg = ldcg4(arow + (size_t)(kt + 1) * 16);
            w_reg = ldcg4(wrow + (size_t)(kt + 1) * 16);
        }
        COMPUTE_TILE(cur);
        if (kt + 1 < nkt) STORE_TILE(cur ^ 1);
        __syncthreads();
    }

#pragma unroll
    for (int r = 0; r < 4; ++r) {
        const int row = m0 + (ty << 2) + r;
        size_t coff;
        if (cmode == 0) {
            coff = (size_t)row * N;
        } else {
            int t = row >> 7, b = row & (BB - 1);
            coff = ((size_t)b * TT + t) * N;
        }
        size_t cinoff = 0;
        if (Cin) {
            int cr = (cinmode == 0) ? row : (((row >> 11) << 7) + (row & (BB - 1)));
            cinoff = (size_t)cr * N;
        }
#pragma unroll
        for (int p = 0; p < 2; ++p) {
            const int col = n0 + (tx << 2) + (p << 1);
            float2 v = upk2(acc[r][p]);
            if (bias) { v.x += bias[col]; v.y += bias[col + 1]; }
            if (Cin)  { float2 ci = *(const float2*)(Cin + cinoff + col); v.x += ci.x; v.y += ci.y; }
            if (act)  { v.x = tanhf(v.x); v.y = tanhf(v.y); }
            *(float2*)(C + coff + col) = v;
        }
    }
}

// ---------------- grid barrier (all NBLK blocks co-resident) ----------------
__device__ __forceinline__ void grid_barrier()
{
    __syncthreads();
    __threadfence();                 // every thread orders its own global stores
    if (threadIdx.x == 0) {
        unsigned int gen = g_bar_gen;
        if (atomicAdd(&g_bar_cnt, 1u) == NBLK - 1u) {
            g_bar_cnt = 0u;
            __threadfence();
            g_bar_gen = gen + 1u;
        } else {
            while (g_bar_gen == gen) { __nanosleep(64); }
        }
    }
    __syncthreads();
}

// ---------------- persistent LSTM recurrence: fused gate GEMM + cell ----------------
// Weights in gate-permuted order (row j*4+g). Each thread owns 4 (row, j) cells:
// acc[r][0]={i,f}, acc[r][1]={g,o}. c state lives in registers across all T steps.
// One grid barrier per step (publish h_all[t]).
__global__ __launch_bounds__(256)
void lstm_recurrence(const float* __restrict__ W, const float* __restrict__ gx,
                     float* __restrict__ h_all, int T)
{
    __shared__ unsigned long long Ad[2][16][PA];
    __shared__ float Ws[2][16][PW];

    const int tid = threadIdx.x;
    const int bx  = blockIdx.x;
    const int m0 = (bx >> 6) << 6;          // 0 or 64
    const int n0 = (bx & 63) << 6;          // perm-col tile: j in [n0/4, n0/4+16)

    const int li = tid >> 2;
    const int lk = (tid & 3) << 2;
    const int ty = tid >> 4;
    const int tx = tid & 15;

    const float* wrow = W + (size_t)(n0 + li) * 1024 + lk;
    const int jj = (n0 >> 2) + tx;

    float cstate[4] = {0.f, 0.f, 0.f, 0.f};

    for (int t = 0; t < T; ++t) {
        const float* hbase = (t == 0) ? g_zero : h_all + (size_t)(t - 1) * BB * 1024;
        const float* arow = hbase + (size_t)(m0 + li) * 1024 + lk;

        float4 a_reg = ldcg4(arow);
        float4 w_reg = ldcg4(wrow);
        STORE_TILE(0);
        __syncthreads();

        unsigned long long acc[4][2];
#pragma unroll
        for (int r = 0; r < 4; ++r) { acc[r][0] = 0ull; acc[r][1] = 0ull; }

        for (int kt = 0; kt < 64; ++kt) {
            const int cur = kt & 1;
            if (kt + 1 < 64) {
                a_reg = ldcg4(arow + (size_t)(kt + 1) * 16);
                w_reg = ldcg4(wrow + (size_t)(kt + 1) * 16);
            }
            COMPUTE_TILE(cur);
            if (kt + 1 < 64) STORE_TILE(cur ^ 1);
            __syncthreads();
        }

        // fused cell epilogue: gates = acc + gx[t]; c in regs; write h
        const float* gxt = gx + (size_t)t * BB * 4096;
        float* ht = h_all + (size_t)t * BB * 1024;
#pragma unroll
        for (int r = 0; r < 4; ++r) {
            const int row = m0 + (ty << 2) + r;
            float4 gv = ldcg4(gxt + (size_t)row * 4096 + n0 + (tx << 2));
            float2 v0 = upk2(acc[r][0]);
            float2 v1 = upk2(acc[r][1]);
            float gi = sigm(v0.x + gv.x);
            float gf = sigm(v0.y + gv.y);
            float gg = tanhf(v1.x + gv.z);
            float go = sigm(v1.y + gv.w);
            float c = gf * cstate[r] + gi * gg;
            cstate[r] = c;
            ht[(size_t)row * 1024 + jj] = go * tanhf(c);
        }

        grid_barrier();
    }
}

// ---------------- one-time weight/bias gate-permutation ----------------
// out[(j*4+g)*ldk + k] = in[(g*1024+j)*ldk + k]
__global__ void permute_w(const float* __restrict__ in, float* __restrict__ out, int ldk)
{
    int ro = blockIdx.x;                 // 0..4095
    int j = ro >> 2, g = ro & 3;
    const float* src = in + (size_t)(g * 1024 + j) * ldk;
    float* dst = out + (size_t)ro * ldk;
    for (int k = threadIdx.x * 4; k < ldk; k += blockDim.x * 4)
        *(float4*)(dst + k) = __ldcg((const float4*)(src + k));
}

__global__ void addperm(const float* __restrict__ a, const float* __restrict__ b,
                        float* __restrict__ o)
{
    int i = blockIdx.x * blockDim.x + threadIdx.x;   // 0..4095 (perm index)
    int j = i >> 2, g = i & 3;
    int s = g * 1024 + j;
    o[i] = a[s] + b[s];
}

// ---------------- host ----------------
extern "C" void kernel_launch(void* const* d_in, const int* in_sizes, int n_in,
                              void* d_out, int out_size)
{
    const float* z      = (const float*)d_in[0];
    const float* x      = (const float*)d_in[1];
    const float* fcz_w  = (const float*)d_in[2];
    const float* fcz_b  = (const float*)d_in[3];
    const float* c_wih  = (const float*)d_in[4];
    const float* c_whh  = (const float*)d_in[5];
    const float* c_bih  = (const float*)d_in[6];
    const float* c_bhh  = (const float*)d_in[7];
    const float* fcc_w  = (const float*)d_in[8];
    const float* fcc_b  = (const float*)d_in[9];
    const float* d0_wih = (const float*)d_in[10];
    const float* d0_whh = (const float*)d_in[11];
    const float* d0_bih = (const float*)d_in[12];
    const float* d0_bhh = (const float*)d_in[13];
    const float* d1_wih = (const float*)d_in[14];
    const float* d1_whh = (const float*)d_in[15];
    const float* d1_bih = (const float*)d_in[16];
    const float* d1_bhh = (const float*)d_in[17];
    const float* out_w  = (const float*)d_in[18];
    const float* out_b  = (const float*)d_in[19];
    float* out = (float*)d_out;

    float *cin, *gxc, *condh, *emb, *gxe, *gx, *h0, *h1;
    float *cwih_p, *cwhh_p, *d0wih_p, *d0whh_p, *d1wih_p, *d1whh_p, *bsum_p;
    cudaGetSymbolAddress((void**)&cin,     g_cin);
    cudaGetSymbolAddress((void**)&gxc,     g_gxc);
    cudaGetSymbolAddress((void**)&condh,   g_condh);
    cudaGetSymbolAddress((void**)&emb,     g_emb);
    cudaGetSymbolAddress((void**)&gxe,     g_gxe);
    cudaGetSymbolAddress((void**)&gx,      g_gx);
    cudaGetSymbolAddress((void**)&h0,      g_h0);
    cudaGetSymbolAddress((void**)&h1,      g_h1);
    cudaGetSymbolAddress((void**)&cwih_p,  g_cwih_p);
    cudaGetSymbolAddress((void**)&cwhh_p,  g_cwhh_p);
    cudaGetSymbolAddress((void**)&d0wih_p, g_d0wih_p);
    cudaGetSymbolAddress((void**)&d0whh_p, g_d0whh_p);
    cudaGetSymbolAddress((void**)&d1wih_p, g_d1wih_p);
    cudaGetSymbolAddress((void**)&d1whh_p, g_d1whh_p);
    cudaGetSymbolAddress((void**)&bsum_p,  g_bsum_p);

    dim3 blk(256);

    // one-time permutes (gate-interleaved row order)
    permute_w<<<4096, 128>>>(c_wih,  cwih_p,  HC);
    permute_w<<<4096, 128>>>(c_whh,  cwhh_p,  HC);
    permute_w<<<4096, 128>>>(d0_wih, d0wih_p, VV + EE);
    permute_w<<<4096, 128>>>(d0_whh, d0whh_p, HD);
    permute_w<<<4096, 128>>>(d1_wih, d1wih_p, HD);
    permute_w<<<4096, 128>>>(d1_whh, d1whh_p, HD);
    addperm<<<16, 256>>>(c_bih,  c_bhh,  bsum_p);
    addperm<<<16, 256>>>(d0_bih, d0_bhh, bsum_p + 4096);
    addperm<<<16, 256>>>(d1_bih, d1_bhh, bsum_p + 8192);

    // ---- conductor ----
    gemm_nt<<<dim3(HC / 64, (SSEQ * BB) / 64), blk>>>(
        z, fcz_w, fcz_b, nullptr, cin, SSEQ * BB, HC, ZZ, ZZ, 1, 0, 0, 0);
    gemm_nt<<<dim3(4 * HC / 64, (SSEQ * BB) / 64), blk>>>(
        cin, cwih_p, bsum_p, nullptr, gxc, SSEQ * BB, 4 * HC, HC, HC, 0, 0, 0, 0);
    lstm_recurrence<<<NBLK, blk>>>(cwhh_p, gxc, condh, SSEQ);
    gemm_nt<<<dim3(EE / 64, (SSEQ * BB) / 64), blk>>>(
        condh, fcc_w, fcc_b, nullptr, emb, SSEQ * BB, EE, HC, HC, 0, 0, 0, 1);
    gemm_nt<<<dim3(4 * HD / 64, (SSEQ * BB) / 64), blk>>>(
        emb, d0wih_p + VV, bsum_p + 4096, nullptr, gxe,
        SSEQ * BB, 4 * HD, EE, VV + EE, 0, 0, 0, 0);

    // ---- decoder layer 0 ----
    gemm_nt<<<dim3(4 * HD / 64, (TT * BB) / 64), blk>>>(
        x, d0wih_p, nullptr, gxe, gx, TT * BB, 4 * HD, VV, VV + EE, 2, 1, 0, 0);
    lstm_recurrence<<<NBLK, blk>>>(d0whh_p, gx, h0, TT);

    // ---- decoder layer 1 ----
    gemm_nt<<<dim3(4 * HD / 64, (TT * BB) / 64), blk>>>(
        h0, d1wih_p, bsum_p + 8192, nullptr, gx, TT * BB, 4 * HD, HD, HD, 0, 0, 0, 0);
    lstm_recurrence<<<NBLK, blk>>>(d1whh_p, gx, h1, TT);

    // ---- output projection (time-major -> [B,T,V]) ----
    gemm_nt<<<dim3(VV / 64, (TT * BB) / 64), blk>>>(
        h1, out_w, out_b, nullptr, out, TT * BB, VV, HD, HD, 0, 0, 1, 0);
}

// round 7
// speedup vs baseline: 1.2302x; 1.0003x over previous
#include <cuda_runtime.h>
#include <cstdint>

#define BB 128
#define SSEQ 16
#define TT 256
#define ZZ 512
#define HC 1024
#define EE 512
#define HD 1024
#define VV 1024
#define NBLK 128

// ---------------- scratch (device globals; zero-init at module load) ----------------
__device__ float g_zero[BB * HD];                       // never written: stays zero
__device__ float g_cin[SSEQ * BB * HC];
__device__ float g_gxc[SSEQ * BB * 4 * HC];             // perm gate order
__device__ float g_condh[SSEQ * BB * HC];
__device__ float g_emb[SSEQ * BB * EE];
__device__ float g_gxe[SSEQ * BB * 4 * HD];             // perm
__device__ float g_gx[TT * BB * 4 * HD];                // perm
__device__ float g_h0[TT * BB * HD];
__device__ float g_h1[TT * BB * HD];
// permuted weights / biases
__device__ float g_cwih_p[4 * HC * HC];
__device__ float g_cwhh_p[4 * HC * HC];
__device__ float g_d0wih_p[4 * HD * (VV + EE)];
__device__ float g_d0whh_p[4 * HD * HD];
__device__ float g_d1wih_p[4 * HD * HD];
__device__ float g_d1whh_p[4 * HD * HD];
__device__ float g_bsum_p[3 * 4 * HD];

// grid-barrier state (monotonic generation; count self-resets)
__device__ volatile unsigned int g_bar_gen;
__device__ unsigned int g_bar_cnt;

// ---------------- packed fp32x2 helpers (SASS FFMA2 path) ----------------
__device__ __forceinline__ unsigned long long ffma2(unsigned long long a,
                                                    unsigned long long b,
                                                    unsigned long long c) {
    unsigned long long d;
    asm("fma.rn.f32x2 %0, %1, %2, %3;" : "=l"(d) : "l"(a), "l"(b), "l"(c));
    return d;
}
__device__ __forceinline__ unsigned long long pk2(float x, float y) {
    unsigned long long r;
    asm("mov.b64 %0, {%1, %2};" : "=l"(r) : "f"(x), "f"(y));
    return r;
}
__device__ __forceinline__ float2 upk2(unsigned long long v) {
    float2 d;
    asm("mov.b64 {%0, %1}, %2;" : "=f"(d.x), "=f"(d.y) : "l"(v));
    return d;
}
__device__ __forceinline__ float4 ldcg4(const float* p) {
    return __ldcg((const float4*)p);
}
__device__ __forceinline__ float sigm(float x) { return 1.f / (1.f + expf(-x)); }

// shared-tile dims (padded: banks conflict-degree 2 = floor; rows stay 16B-aligned)
#define PA 66
#define PW 68

// store one k-tile of A (duplicated pairs) and W into smem buffer `buf`
#define STORE_TILE(buf)                                            \
    do {                                                           \
        Ad[buf][lk + 0][li] = pk2(a_reg.x, a_reg.x);               \
        Ad[buf][lk + 1][li] = pk2(a_reg.y, a_reg.y);               \
        Ad[buf][lk + 2][li] = pk2(a_reg.z, a_reg.z);               \
        Ad[buf][lk + 3][li] = pk2(a_reg.w, a_reg.w);               \
        Ws[buf][lk + 0][li] = w_reg.x;                             \
        Ws[buf][lk + 1][li] = w_reg.y;                             \
        Ws[buf][lk + 2][li] = w_reg.z;                             \
        Ws[buf][lk + 3][li] = w_reg.w;                             \
    } while (0)

#define COMPUTE_TILE(buf)                                                     \
    do {                                                                      \
        _Pragma("unroll")                                                     \
        for (int k = 0; k < 16; ++k) {                                        \
            ulonglong2 a01 = *(const ulonglong2*)&Ad[buf][k][(ty << 2)];      \
            ulonglong2 a23 = *(const ulonglong2*)&Ad[buf][k][(ty << 2) + 2];  \
            ulonglong2 w01 = *(const ulonglong2*)&Ws[buf][k][(tx << 2)];      \
            acc[0][0] = ffma2(a01.x, w01.x, acc[0][0]);                       \
            acc[0][1] = ffma2(a01.x, w01.y, acc[0][1]);                       \
            acc[1][0] = ffma2(a01.y, w01.x, acc[1][0]);                       \
            acc[1][1] = ffma2(a01.y, w01.y, acc[1][1]);                       \
            acc[2][0] = ffma2(a23.x, w01.x, acc[2][0]);                       \
            acc[2][1] = ffma2(a23.x, w01.y, acc[2][1]);                       \
            acc[3][0] = ffma2(a23.y, w01.x, acc[3][0]);                       \
            acc[3][1] = ffma2(a23.y, w01.y, acc[3][1]);                       \
        }                                                                     \
    } while (0)

// ---------------- generic NT GEMM (double-buffered) ----------------
// amode: 0 = A row m;  1 = z-gather (m = s*BB+b reads z row b*SSEQ+s);
//        2 = prev-x   (m = t*BB+b reads x row b*TT+t-1, zeros at t==0)
// cinmode: 0 = Cin row m; 1 = Cin row (t>>4)*BB+b
// cmode:   0 = C row m;   1 = C row (b*TT+t)
// act:     0 = none;      1 = tanh
__global__ __launch_bounds__(256, 2)
void gemm_nt(const float* __restrict__ A, const float* __restrict__ W,
             const float* __restrict__ bias, const float* __restrict__ Cin,
             float* __restrict__ C,
             int M, int N, int K, int ldw,
             int amode, int cinmode, int cmode, int act)
{
    __shared__ unsigned long long Ad[2][16][PA];
    __shared__ float Ws[2][16][PW];

    const int tid = threadIdx.x;
    const int m0 = blockIdx.y << 6;
    const int n0 = blockIdx.x << 6;

    const int li = tid >> 2;
    const int lk = (tid & 3) << 2;
    const int ty = tid >> 4;
    const int tx = tid & 15;

    const int m = m0 + li;
    const float* arow;
    if (amode == 0) {
        arow = A + (size_t)m * K;
    } else if (amode == 1) {
        int b = m & (BB - 1), s = m >> 7;
        arow = A + ((size_t)b * SSEQ + s) * K;
    } else {
        int t = m >> 7, b = m & (BB - 1);
        arow = (t == 0) ? g_zero : A + ((size_t)b * TT + (t - 1)) * K;
    }
    arow += lk;
    const float* wrow = W + (size_t)(n0 + li) * ldw + lk;

    const int nkt = K >> 4;
    float4 a_reg = ldcg4(arow);
    float4 w_reg = ldcg4(wrow);
    STORE_TILE(0);
    __syncthreads();

    unsigned long long acc[4][2];
#pragma unroll
    for (int r = 0; r < 4; ++r) { acc[r][0] = 0ull; acc[r][1] = 0ull; }

    for (int kt = 0; kt < nkt; ++kt) {
        const int cur = kt & 1;
        if (kt + 1 < nkt) {
            a_reg = ldcg4(arow + (size_t)(kt + 1) * 16);
            w_reg = ldcg4(wrow + (size_t)(kt + 1) * 16);
        }
        COMPUTE_TILE(cur);
        if (kt + 1 < nkt) STORE_TILE(cur ^ 1);
        __syncthreads();
    }

#pragma unroll
    for (int r = 0; r < 4; ++r) {
        const int row = m0 + (ty << 2) + r;
        size_t coff;
        if (cmode == 0) {
            coff = (size_t)row * N;
        } else {
            int t = row >> 7, b = row & (BB - 1);
            coff = ((size_t)b * TT + t) * N;
        }
        size_t cinoff = 0;
        if (Cin) {
            int cr = (cinmode == 0) ? row : (((row >> 11) << 7) + (row & (BB - 1)));
            cinoff = (size_t)cr * N;
        }
#pragma unroll
        for (int p = 0; p < 2; ++p) {
            const int col = n0 + (tx << 2) + (p << 1);
            float2 v = upk2(acc[r][p]);
            if (bias) { v.x += bias[col]; v.y += bias[col + 1]; }
            if (Cin)  { float2 ci = *(const float2*)(Cin + cinoff + col); v.x += ci.x; v.y += ci.y; }
            if (act)  { v.x = tanhf(v.x); v.y = tanhf(v.y); }
            *(float2*)(C + coff + col) = v;
        }
    }
}

// ---------------- grid barrier (all NBLK blocks co-resident) ----------------
__device__ __forceinline__ void grid_barrier()
{
    __syncthreads();
    __threadfence();                 // every thread orders its own global stores
    if (threadIdx.x == 0) {
        unsigned int gen = g_bar_gen;
        if (atomicAdd(&g_bar_cnt, 1u) == NBLK - 1u) {
            g_bar_cnt = 0u;
            __threadfence();
            g_bar_gen = gen + 1u;
        } else {
            while (g_bar_gen == gen) { __nanosleep(64); }
        }
    }
    __syncthreads();
}

// ---------------- persistent LSTM recurrence: fused gate GEMM + cell ----------------
// Weights in gate-permuted order (row j*4+g). Each thread owns 4 (row, j) cells:
// acc[r][0]={i,f}, acc[r][1]={g,o}. c state lives in registers across all T steps.
// One grid barrier per step (publish h_all[t]).
__global__ __launch_bounds__(256)
void lstm_recurrence(const float* __restrict__ W, const float* __restrict__ gx,
                     float* __restrict__ h_all, int T)
{
    __shared__ unsigned long long Ad[2][16][PA];
    __shared__ float Ws[2][16][PW];

    const int tid = threadIdx.x;
    const int bx  = blockIdx.x;
    const int m0 = (bx >> 6) << 6;          // 0 or 64
    const int n0 = (bx & 63) << 6;          // perm-col tile: j in [n0/4, n0/4+16)

    const int li = tid >> 2;
    const int lk = (tid & 3) << 2;
    const int ty = tid >> 4;
    const int tx = tid & 15;

    const float* wrow = W + (size_t)(n0 + li) * 1024 + lk;
    const int jj = (n0 >> 2) + tx;

    float cstate[4] = {0.f, 0.f, 0.f, 0.f};

    for (int t = 0; t < T; ++t) {
        const float* hbase = (t == 0) ? g_zero : h_all + (size_t)(t - 1) * BB * 1024;
        const float* arow = hbase + (size_t)(m0 + li) * 1024 + lk;

        float4 a_reg = ldcg4(arow);
        float4 w_reg = ldcg4(wrow);
        STORE_TILE(0);
        __syncthreads();

        unsigned long long acc[4][2];
#pragma unroll
        for (int r = 0; r < 4; ++r) { acc[r][0] = 0ull; acc[r][1] = 0ull; }

        for (int kt = 0; kt < 64; ++kt) {
            const int cur = kt & 1;
            if (kt + 1 < 64) {
                a_reg = ldcg4(arow + (size_t)(kt + 1) * 16);
                w_reg = ldcg4(wrow + (size_t)(kt + 1) * 16);
            }
            COMPUTE_TILE(cur);
            if (kt + 1 < 64) STORE_TILE(cur ^ 1);
            __syncthreads();
        }

        // fused cell epilogue: gates = acc + gx[t]; c in regs; write h
        const float* gxt = gx + (size_t)t * BB * 4096;
        float* ht = h_all + (size_t)t * BB * 1024;
#pragma unroll
        for (int r = 0; r < 4; ++r) {
            const int row = m0 + (ty << 2) + r;
            float4 gv = ldcg4(gxt + (size_t)row * 4096 + n0 + (tx << 2));
            float2 v0 = upk2(acc[r][0]);
            float2 v1 = upk2(acc[r][1]);
            float gi = sigm(v0.x + gv.x);
            float gf = sigm(v0.y + gv.y);
            float gg = tanhf(v1.x + gv.z);
            float go = sigm(v1.y + gv.w);
            float c = gf * cstate[r] + gi * gg;
            cstate[r] = c;
            ht[(size_t)row * 1024 + jj] = go * tanhf(c);
        }

        grid_barrier();
    }
}

// ---------------- one-time weight/bias gate-permutation ----------------
// out[(j*4+g)*ldk + k] = in[(g*1024+j)*ldk + k]
__global__ void permute_w(const float* __restrict__ in, float* __restrict__ out, int ldk)
{
    int ro = blockIdx.x;                 // 0..4095
    int j = ro >> 2, g = ro & 3;
    const float* src = in + (size_t)(g * 1024 + j) * ldk;
    float* dst = out + (size_t)ro * ldk;
    for (int k = threadIdx.x * 4; k < ldk; k += blockDim.x * 4)
        *(float4*)(dst + k) = __ldcg((const float4*)(src + k));
}

__global__ void addperm(const float* __restrict__ a, const float* __restrict__ b,
                        float* __restrict__ o)
{
    int i = blockIdx.x * blockDim.x + threadIdx.x;   // 0..4095 (perm index)
    int j = i >> 2, g = i & 3;
    int s = g * 1024 + j;
    o[i] = a[s] + b[s];
}

// ---------------- host ----------------
extern "C" void kernel_launch(void* const* d_in, const int* in_sizes, int n_in,
                              void* d_out, int out_size)
{
    const float* z      = (const float*)d_in[0];
    const float* x      = (const float*)d_in[1];
    const float* fcz_w  = (const float*)d_in[2];
    const float* fcz_b  = (const float*)d_in[3];
    const float* c_wih  = (const float*)d_in[4];
    const float* c_whh  = (const float*)d_in[5];
    const float* c_bih  = (const float*)d_in[6];
    const float* c_bhh  = (const float*)d_in[7];
    const float* fcc_w  = (const float*)d_in[8];
    const float* fcc_b  = (const float*)d_in[9];
    const float* d0_wih = (const float*)d_in[10];
    const float* d0_whh = (const float*)d_in[11];
    const float* d0_bih = (const float*)d_in[12];
    const float* d0_bhh = (const float*)d_in[13];
    const float* d1_wih = (const float*)d_in[14];
    const float* d1_whh = (const float*)d_in[15];
    const float* d1_bih = (const float*)d_in[16];
    const float* d1_bhh = (const float*)d_in[17];
    const float* out_w  = (const float*)d_in[18];
    const float* out_b  = (const float*)d_in[19];
    float* out = (float*)d_out;

    float *cin, *gxc, *condh, *emb, *gxe, *gx, *h0, *h1;
    float *cwih_p, *cwhh_p, *d0wih_p, *d0whh_p, *d1wih_p, *d1whh_p, *bsum_p;
    cudaGetSymbolAddress((void**)&cin,     g_cin);
    cudaGetSymbolAddress((void**)&gxc,     g_gxc);
    cudaGetSymbolAddress((void**)&condh,   g_condh);
    cudaGetSymbolAddress((void**)&emb,     g_emb);
    cudaGetSymbolAddress((void**)&gxe,     g_gxe);
    cudaGetSymbolAddress((void**)&gx,      g_gx);
    cudaGetSymbolAddress((void**)&h0,      g_h0);
    cudaGetSymbolAddress((void**)&h1,      g_h1);
    cudaGetSymbolAddress((void**)&cwih_p,  g_cwih_p);
    cudaGetSymbolAddress((void**)&cwhh_p,  g_cwhh_p);
    cudaGetSymbolAddress((void**)&d0wih_p, g_d0wih_p);
    cudaGetSymbolAddress((void**)&d0whh_p, g_d0whh_p);
    cudaGetSymbolAddress((void**)&d1wih_p, g_d1wih_p);
    cudaGetSymbolAddress((void**)&d1whh_p, g_d1whh_p);
    cudaGetSymbolAddress((void**)&bsum_p,  g_bsum_p);

    dim3 blk(256);

    // one-time permutes (gate-interleaved row order)
    permute_w<<<4096, 128>>>(c_wih,  cwih_p,  HC);
    permute_w<<<4096, 128>>>(c_whh,  cwhh_p,  HC);
    permute_w<<<4096, 128>>>(d0_wih, d0wih_p, VV + EE);
    permute_w<<<4096, 128>>>(d0_whh, d0whh_p, HD);
    permute_w<<<4096, 128>>>(d1_wih, d1wih_p, HD);
    permute_w<<<4096, 128>>>(d1_whh, d1whh_p, HD);
    addperm<<<16, 256>>>(c_bih,  c_bhh,  bsum_p);
    addperm<<<16, 256>>>(d0_bih, d0_bhh, bsum_p + 4096);
    addperm<<<16, 256>>>(d1_bih, d1_bhh, bsum_p + 8192);

    // ---- conductor ----
    gemm_nt<<<dim3(HC / 64, (SSEQ * BB) / 64), blk>>>(
        z, fcz_w, fcz_b, nullptr, cin, SSEQ * BB, HC, ZZ, ZZ, 1, 0, 0, 0);
    gemm_nt<<<dim3(4 * HC / 64, (SSEQ * BB) / 64), blk>>>(
        cin, cwih_p, bsum_p, nullptr, gxc, SSEQ * BB, 4 * HC, HC, HC, 0, 0, 0, 0);
    lstm_recurrence<<<NBLK, blk>>>(cwhh_p, gxc, condh, SSEQ);
    gemm_nt<<<dim3(EE / 64, (SSEQ * BB) / 64), blk>>>(
        condh, fcc_w, fcc_b, nullptr, emb, SSEQ * BB, EE, HC, HC, 0, 0, 0, 1);
    gemm_nt<<<dim3(4 * HD / 64, (SSEQ * BB) / 64), blk>>>(
        emb, d0wih_p + VV, bsum_p + 4096, nullptr, gxe,
        SSEQ * BB, 4 * HD, EE, VV + EE, 0, 0, 0, 0);

    // ---- decoder layer 0 ----
    gemm_nt<<<dim3(4 * HD / 64, (TT * BB) / 64), blk>>>(
        x, d0wih_p, nullptr, gxe, gx, TT * BB, 4 * HD, VV, VV + EE, 2, 1, 0, 0);
    lstm_recurrence<<<NBLK, blk>>>(d0whh_p, gx, h0, TT);

    // ---- decoder layer 1 ----
    gemm_nt<<<dim3(4 * HD / 64, (TT * BB) / 64), blk>>>(
        h0, d1wih_p, bsum_p + 8192, nullptr, gx, TT * BB, 4 * HD, HD, HD, 0, 0, 0, 0);
    lstm_recurrence<<<NBLK, blk>>>(d1whh_p, gx, h1, TT);

    // ---- output projection (time-major -> [B,T,V]) ----
    gemm_nt<<<dim3(VV / 64, (TT * BB) / 64), blk>>>(
        h1, out_w, out_b, nullptr, out, TT * BB, VV, HD, HD, 0, 0, 1, 0);
}

// round 9
// speedup vs baseline: 1.7217x; 1.3996x over previous
#include <cuda_runtime.h>
#include <cuda_bf16.h>
#include <cstdint>

#define BB 128
#define SSEQ 16
#define TT 256
#define ZZ 512
#define HC 1024
#define EE 512
#define HD 1024
#define VV 1024
#define NBLK 128

// ---------------- scratch (device globals; zero-init at module load) ----------------
__device__ float g_zero[BB * HD];                       // never written: stays zero
__device__ float g_cin[SSEQ * BB * HC];
__device__ float g_gxc[SSEQ * BB * 4 * HC];             // perm gate order
__device__ float g_condh[SSEQ * BB * HC];
__device__ float g_emb[SSEQ * BB * EE];
__device__ float g_gxe[SSEQ * BB * 4 * HD];             // perm
__device__ float g_gx[TT * BB * 4 * HD];                // perm
__device__ float g_h0[TT * BB * HD];
__device__ float g_h1[TT * BB * HD];
// fp32 permuted weights (FFMA2 consumers)
__device__ float g_cwih_p[4 * HC * HC];
__device__ float g_cwhh_p[4 * HC * HC];
__device__ float g_d0wih_p[4 * HD * (VV + EE)];
__device__ float g_d0whh_p[4 * HD * HD];
__device__ float g_d1whh_p[4 * HD * HD];
__device__ float g_bsum_p[3 * 4 * HD];
// bf16 hi/lo split weights (mma consumers)
__device__ __align__(16) __nv_bfloat16 g_d0wih_hi[4 * HD * VV];
__device__ __align__(16) __nv_bfloat16 g_d0wih_lo[4 * HD * VV];
__device__ __align__(16) __nv_bfloat16 g_d1wih_hi[4 * HD * HD];
__device__ __align__(16) __nv_bfloat16 g_d1wih_lo[4 * HD * HD];
__device__ __align__(16) __nv_bfloat16 g_outw_hi[VV * HD];
__device__ __align__(16) __nv_bfloat16 g_outw_lo[VV * HD];

// grid-barrier state
__device__ volatile unsigned int g_bar_gen;
__device__ unsigned int g_bar_cnt;

// ---------------- packed fp32x2 helpers (SASS FFMA2 path) ----------------
__device__ __forceinline__ unsigned long long ffma2(unsigned long long a,
                                                    unsigned long long b,
                                                    unsigned long long c) {
    unsigned long long d;
    asm("fma.rn.f32x2 %0, %1, %2, %3;" : "=l"(d) : "l"(a), "l"(b), "l"(c));
    return d;
}
__device__ __forceinline__ unsigned long long pk2(float x, float y) {
    unsigned long long r;
    asm("mov.b64 %0, {%1, %2};" : "=l"(r) : "f"(x), "f"(y));
    return r;
}
__device__ __forceinline__ float2 upk2(unsigned long long v) {
    float2 d;
    asm("mov.b64 {%0, %1}, %2;" : "=f"(d.x), "=f"(d.y) : "l"(v));
    return d;
}
__device__ __forceinline__ float4 ldcg4(const float* p) {
    return __ldcg((const float4*)(p));
}
__device__ __forceinline__ float sigm(float x) { return 1.f / (1.f + expf(-x)); }

__device__ __forceinline__ uint32_t smem_u32(const void* p) {
    uint32_t a;
    asm("{ .reg .u64 t; cvta.to.shared.u64 t, %1; cvt.u32.u64 %0, t; }" : "=r"(a) : "l"(p));
    return a;
}
__device__ __forceinline__ uint32_t pack_bf16(__nv_bfloat16 a, __nv_bfloat16 b) {
    return (uint32_t)__bfloat16_as_ushort(a) | ((uint32_t)__bfloat16_as_ushort(b) << 16);
}
__device__ __forceinline__ void split2(float x, float y, uint32_t& hp, uint32_t& lp) {
    __nv_bfloat16 hx = __float2bfloat16(x), hy = __float2bfloat16(y);
    __nv_bfloat16 lx = __float2bfloat16(x - __bfloat162float(hx));
    __nv_bfloat16 ly = __float2bfloat16(y - __bfloat162float(hy));
    hp = pack_bf16(hx, hy);
    lp = pack_bf16(lx, ly);
}

// ---------------- mma.sync (HMMA) primitives — baseline PTX, legal on compute_103 ----------------
#define MMA_BF16(d, a, b0, b1)                                                  \
    asm volatile("mma.sync.aligned.m16n8k16.row.col.f32.bf16.bf16.f32 "         \
        "{%0,%1,%2,%3}, {%4,%5,%6,%7}, {%8,%9}, {%0,%1,%2,%3};"                 \
        : "+f"((d)[0]), "+f"((d)[1]), "+f"((d)[2]), "+f"((d)[3])                \
        : "r"((a)[0]), "r"((a)[1]), "r"((a)[2]), "r"((a)[3]), "r"(b0), "r"(b1))

#define LDMX4(r, addr)                                                          \
    asm volatile("ldmatrix.sync.aligned.m8n8.x4.shared.b16 {%0,%1,%2,%3}, [%4];" \
        : "=r"((r)[0]), "=r"((r)[1]), "=r"((r)[2]), "=r"((r)[3]) : "r"(addr))

// ---------------- HMMA GEMM: C[M,N] = gather(A)[M,K] * W[N,K]^T (+bias)(+Cin) ----------------
// 128x128 tile per CTA, 8 warps (2 m x 4 n), warp tile 64x32, K-chunk 32.
// A fp32 split to bf16 hi/lo in transit; W pre-split. 3 mmas per (frag,k16): hh, hl, lh.
// smem per stage (32KB): [AH 8K][AL 8K][WH 8K][WL 8K]; 2 stages = 64KB dynamic.
// Rows of 64B (32 bf16); 16B-chunk XOR swizzle: phys_chunk = logical ^ (row & 3).
// amode: 0 = A row m; 2 = prev-x gather (m=t*BB+b reads x row b*TT+t-1; zeros at t==0).
// Cin (if set): row (t>>4)*BB+b (embedding addend).  cmode: 0 = row m; 1 = row (b*TT+t).
#define MST 32768
__global__ __launch_bounds__(256, 1)
void gemm_mma(const float* __restrict__ A,
              const __nv_bfloat16* __restrict__ Whi,
              const __nv_bfloat16* __restrict__ Wlo,
              const float* __restrict__ bias, const float* __restrict__ Cin,
              float* __restrict__ C,
              int K, int N, int amode, int cmode)
{
    extern __shared__ char sm[];
    const uint32_t sb = smem_u32(sm);
    const int tid = threadIdx.x;
    const int lane = tid & 31;
    const int wid = tid >> 5;
    const int warp_m = wid & 1;
    const int warp_n = wid >> 1;
    const int m0 = blockIdx.y << 7;
    const int n0 = blockIdx.x << 7;

    // ---- loader roles: row = tid>>1 (0..127), half = tid&1 (k-halves of 64B row) ----
    const int lrow = tid >> 1;
    const int half = tid & 1;

    const float* arow;
    {
        int m = m0 + lrow;
        if (amode == 0) {
            arow = A + (size_t)m * K;
        } else {
            int t = m >> 7, b = m & 127;
            arow = (t == 0) ? g_zero : A + ((size_t)b * TT + (t - 1)) * 1024;
        }
    }
    const uint4* whrow = (const uint4*)(Whi + (size_t)(n0 + lrow) * K);
    const uint4* wlrow = (const uint4*)(Wlo + (size_t)(n0 + lrow) * K);

    // smem store offsets (shared by A and W regions): logical chunks half*2, half*2+1
    const uint32_t sst0 = (uint32_t)lrow * 64u + (uint32_t)(((half * 2)     ^ (lrow & 3)) << 4);
    const uint32_t sst1 = (uint32_t)lrow * 64u + (uint32_t)(((half * 2 + 1) ^ (lrow & 3)) << 4);

    // ---- ldmatrix source addresses (stage 0; add stage offset per chunk) ----
    uint32_t a_addr[4][2], b_addr[2][2];
    {
        int ar = warp_m * 64 + (lane & 7) + (((lane >> 3) & 1) << 3);
        int akh = lane >> 4;
        int br = warp_n * 32 + (lane & 7) + ((lane >> 4) << 3);
        int bkh = (lane >> 3) & 1;
#pragma unroll
        for (int mi = 0; mi < 4; ++mi)
#pragma unroll
            for (int kk = 0; kk < 2; ++kk) {
                int row = ar + mi * 16;
                a_addr[mi][kk] = sb + (uint32_t)row * 64u
                               + (uint32_t)((((kk << 1) | akh) ^ (row & 3)) << 4);
            }
#pragma unroll
        for (int ng = 0; ng < 2; ++ng)
#pragma unroll
            for (int kk = 0; kk < 2; ++kk) {
                int row = br + ng * 16;
                b_addr[ng][kk] = sb + 16384u + (uint32_t)row * 64u
                               + (uint32_t)((((kk << 1) | bkh) ^ (row & 3)) << 4);
            }
    }

    float acc[4][4][4];
#pragma unroll
    for (int mi = 0; mi < 4; ++mi)
#pragma unroll
        for (int nf = 0; nf < 4; ++nf)
#pragma unroll
            for (int q = 0; q < 4; ++q) acc[mi][nf][q] = 0.f;

    const int NC = K >> 5;
    float4 pa[4];
    uint4 pwh[2], pwl[2];

    // prefetch chunk 0
#pragma unroll
    for (int i = 0; i < 4; ++i) pa[i] = ldcg4(arow + half * 16 + i * 4);
#pragma unroll
    for (int j = 0; j < 2; ++j) {
        pwh[j] = __ldcg(whrow + half * 2 + j);
        pwl[j] = __ldcg(wlrow + half * 2 + j);
    }
    // store chunk 0 -> stage 0
    {
        uint32_t h0a, l0a, h0b, l0b, h1a, l1a, h1b, l1b;
        split2(pa[0].x, pa[0].y, h0a, l0a); split2(pa[0].z, pa[0].w, h0b, l0b);
        split2(pa[1].x, pa[1].y, h1a, l1a); split2(pa[1].z, pa[1].w, h1b, l1b);
        *(uint4*)(sm + sst0)         = make_uint4(h0a, h0b, h1a, h1b);
        *(uint4*)(sm + 8192 + sst0)  = make_uint4(l0a, l0b, l1a, l1b);
        split2(pa[2].x, pa[2].y, h0a, l0a); split2(pa[2].z, pa[2].w, h0b, l0b);
        split2(pa[3].x, pa[3].y, h1a, l1a); split2(pa[3].z, pa[3].w, h1b, l1b);
        *(uint4*)(sm + sst1)         = make_uint4(h0a, h0b, h1a, h1b);
        *(uint4*)(sm + 8192 + sst1)  = make_uint4(l0a, l0b, l1a, l1b);
        *(uint4*)(sm + 16384 + sst0) = pwh[0];
        *(uint4*)(sm + 16384 + sst1) = pwh[1];
        *(uint4*)(sm + 24576 + sst0) = pwl[0];
        *(uint4*)(sm + 24576 + sst1) = pwl[1];
    }
    __syncthreads();

    for (int c = 0; c < NC; ++c) {
        const int cur = c & 1;
        const uint32_t soff = (uint32_t)cur * MST;
        if (c + 1 < NC) {
#pragma unroll
            for (int i = 0; i < 4; ++i)
                pa[i] = ldcg4(arow + (c + 1) * 32 + half * 16 + i * 4);
#pragma unroll
            for (int j = 0; j < 2; ++j) {
                pwh[j] = __ldcg(whrow + (c + 1) * 4 + half * 2 + j);
                pwl[j] = __ldcg(wlrow + (c + 1) * 4 + half * 2 + j);
            }
        }

#pragma unroll
        for (int kk = 0; kk < 2; ++kk) {
            uint32_t ah[4][4], al[4][4], bh[2][4], bl[2][4];
#pragma unroll
            for (int mi = 0; mi < 4; ++mi) {
                LDMX4(ah[mi], a_addr[mi][kk] + soff);
                LDMX4(al[mi], a_addr[mi][kk] + soff + 8192u);
            }
#pragma unroll
            for (int ng = 0; ng < 2; ++ng) {
                LDMX4(bh[ng], b_addr[ng][kk] + soff);
                LDMX4(bl[ng], b_addr[ng][kk] + soff + 8192u);
            }
#pragma unroll
            for (int mi = 0; mi < 4; ++mi) {
#pragma unroll
                for (int nf = 0; nf < 4; ++nf) {
                    const int ng = nf >> 1;
                    const int p = (nf & 1) << 1;
                    MMA_BF16(acc[mi][nf], ah[mi], bh[ng][p], bh[ng][p + 1]);
                    MMA_BF16(acc[mi][nf], ah[mi], bl[ng][p], bl[ng][p + 1]);
                    MMA_BF16(acc[mi][nf], al[mi], bh[ng][p], bh[ng][p + 1]);
                }
            }
        }

        if (c + 1 < NC) {
            char* d = sm + (cur ^ 1) * MST;
            uint32_t h0a, l0a, h0b, l0b, h1a, l1a, h1b, l1b;
            split2(pa[0].x, pa[0].y, h0a, l0a); split2(pa[0].z, pa[0].w, h0b, l0b);
            split2(pa[1].x, pa[1].y, h1a, l1a); split2(pa[1].z, pa[1].w, h1b, l1b);
            *(uint4*)(d + sst0)         = make_uint4(h0a, h0b, h1a, h1b);
            *(uint4*)(d + 8192 + sst0)  = make_uint4(l0a, l0b, l1a, l1b);
            split2(pa[2].x, pa[2].y, h0a, l0a); split2(pa[2].z, pa[2].w, h0b, l0b);
            split2(pa[3].x, pa[3].y, h1a, l1a); split2(pa[3].z, pa[3].w, h1b, l1b);
            *(uint4*)(d + sst1)         = make_uint4(h0a, h0b, h1a, h1b);
            *(uint4*)(d + 8192 + sst1)  = make_uint4(l0a, l0b, l1a, l1b);
            *(uint4*)(d + 16384 + sst0) = pwh[0];
            *(uint4*)(d + 16384 + sst1) = pwh[1];
            *(uint4*)(d + 24576 + sst0) = pwl[0];
            *(uint4*)(d + 24576 + sst1) = pwl[1];
        }
        __syncthreads();
    }

    // ---- epilogue ----
    const int grp = lane >> 2;
    const int cl  = (lane & 3) << 1;
#pragma unroll
    for (int mi = 0; mi < 4; ++mi) {
#pragma unroll
        for (int h = 0; h < 2; ++h) {
            const int row = m0 + warp_m * 64 + mi * 16 + grp + h * 8;
            size_t coff;
            if (cmode == 0) {
                coff = (size_t)row * N;
            } else {
                int t = row >> 7, b = row & 127;
                coff = ((size_t)b * TT + t) * N;
            }
            size_t cinoff = 0;
            if (Cin) {
                int cr = ((row >> 11) << 7) + (row & 127);
                cinoff = (size_t)cr * N;
            }
#pragma unroll
            for (int nf = 0; nf < 4; ++nf) {
                const int col = n0 + warp_n * 32 + nf * 8 + cl;
                float2 v = make_float2(acc[mi][nf][h * 2], acc[mi][nf][h * 2 + 1]);
                if (bias) { v.x += bias[col]; v.y += bias[col + 1]; }
                if (Cin)  {
                    float2 ci = *(const float2*)(Cin + cinoff + col);
                    v.x += ci.x; v.y += ci.y;
                }
                *(float2*)(C + coff + col) = v;
            }
        }
    }
}

// ---------------- FFMA2 tile macros (small GEMMs + recurrence) ----------------
#define PA 66
#define PW 68
#define STORE_TILE(buf)                                            \
    do {                                                           \
        Ad[buf][lk + 0][li] = pk2(a_reg.x, a_reg.x);               \
        Ad[buf][lk + 1][li] = pk2(a_reg.y, a_reg.y);               \
        Ad[buf][lk + 2][li] = pk2(a_reg.z, a_reg.z);               \
        Ad[buf][lk + 3][li] = pk2(a_reg.w, a_reg.w);               \
        Ws[buf][lk + 0][li] = w_reg.x;                             \
        Ws[buf][lk + 1][li] = w_reg.y;                             \
        Ws[buf][lk + 2][li] = w_reg.z;                             \
        Ws[buf][lk + 3][li] = w_reg.w;                             \
    } while (0)

#define COMPUTE_TILE(buf)                                                     \
    do {                                                                      \
        _Pragma("unroll")                                                     \
        for (int k = 0; k < 16; ++k) {                                        \
            ulonglong2 a01 = *(const ulonglong2*)&Ad[buf][k][(ty << 2)];      \
            ulonglong2 a23 = *(const ulonglong2*)&Ad[buf][k][(ty << 2) + 2];  \
            ulonglong2 w01 = *(const ulonglong2*)&Ws[buf][k][(tx << 2)];      \
            acc[0][0] = ffma2(a01.x, w01.x, acc[0][0]);                       \
            acc[0][1] = ffma2(a01.x, w01.y, acc[0][1]);                       \
            acc[1][0] = ffma2(a01.y, w01.x, acc[1][0]);                       \
            acc[1][1] = ffma2(a01.y, w01.y, acc[1][1]);                       \
            acc[2][0] = ffma2(a23.x, w01.x, acc[2][0]);                       \
            acc[2][1] = ffma2(a23.x, w01.y, acc[2][1]);                       \
            acc[3][0] = ffma2(a23.y, w01.x, acc[3][0]);                       \
            acc[3][1] = ffma2(a23.y, w01.y, acc[3][1]);                       \
        }                                                                     \
    } while (0)

// ---------------- generic FFMA2 NT GEMM (small projections) ----------------
__global__ __launch_bounds__(256, 2)
void gemm_nt(const float* __restrict__ A, const float* __restrict__ W,
             const float* __restrict__ bias, const float* __restrict__ Cin,
             float* __restrict__ C,
             int M, int N, int K, int ldw,
             int amode, int cinmode, int cmode, int act)
{
    __shared__ unsigned long long Ad[2][16][PA];
    __shared__ float Ws[2][16][PW];

    const int tid = threadIdx.x;
    const int m0 = blockIdx.y << 6;
    const int n0 = blockIdx.x << 6;

    const int li = tid >> 2;
    const int lk = (tid & 3) << 2;
    const int ty = tid >> 4;
    const int tx = tid & 15;

    const int m = m0 + li;
    const float* arow;
    if (amode == 0) {
        arow = A + (size_t)m * K;
    } else if (amode == 1) {
        int b = m & (BB - 1), s = m >> 7;
        arow = A + ((size_t)b * SSEQ + s) * K;
    } else {
        int t = m >> 7, b = m & (BB - 1);
        arow = (t == 0) ? g_zero : A + ((size_t)b * TT + (t - 1)) * K;
    }
    arow += lk;
    const float* wrow = W + (size_t)(n0 + li) * ldw + lk;

    const int nkt = K >> 4;
    float4 a_reg = ldcg4(arow);
    float4 w_reg = ldcg4(wrow);
    STORE_TILE(0);
    __syncthreads();

    unsigned long long acc[4][2];
#pragma unroll
    for (int r = 0; r < 4; ++r) { acc[r][0] = 0ull; acc[r][1] = 0ull; }

    for (int kt = 0; kt < nkt; ++kt) {
        const int cur = kt & 1;
        if (kt + 1 < nkt) {
            a_reg = ldcg4(arow + (size_t)(kt + 1) * 16);
            w_reg = ldcg4(wrow + (size_t)(kt + 1) * 16);
        }
        COMPUTE_TILE(cur);
        if (kt + 1 < nkt) STORE_TILE(cur ^ 1);
        __syncthreads();
    }

#pragma unroll
    for (int r = 0; r < 4; ++r) {
        const int row = m0 + (ty << 2) + r;
        size_t coff;
        if (cmode == 0) {
            coff = (size_t)row * N;
        } else {
            int t = row >> 7, b = row & (BB - 1);
            coff = ((size_t)b * TT + t) * N;
        }
        size_t cinoff = 0;
        if (Cin) {
            int cr = (cinmode == 0) ? row : (((row >> 11) << 7) + (row & (BB - 1)));
            cinoff = (size_t)cr * N;
        }
#pragma unroll
        for (int p = 0; p < 2; ++p) {
            const int col = n0 + (tx << 2) + (p << 1);
            float2 v = upk2(acc[r][p]);
            if (bias) { v.x += bias[col]; v.y += bias[col + 1]; }
            if (Cin)  { float2 ci = *(const float2*)(Cin + cinoff + col); v.x += ci.x; v.y += ci.y; }
            if (act)  { v.x = tanhf(v.x); v.y = tanhf(v.y); }
            *(float2*)(C + coff + col) = v;
        }
    }
}

// ---------------- grid barrier (all NBLK blocks co-resident) ----------------
__device__ __forceinline__ void grid_barrier()
{
    __syncthreads();
    __threadfence();
    if (threadIdx.x == 0) {
        unsigned int gen = g_bar_gen;
        if (atomicAdd(&g_bar_cnt, 1u) == NBLK - 1u) {
            g_bar_cnt = 0u;
            __threadfence();
            g_bar_gen = gen + 1u;
        } else {
            while (g_bar_gen == gen) { __nanosleep(64); }
        }
    }
    __syncthreads();
}

// ---------------- persistent LSTM recurrence: fused gate GEMM + cell ----------------
__global__ __launch_bounds__(256)
void lstm_recurrence(const float* __restrict__ W, const float* __restrict__ gx,
                     float* __restrict__ h_all, int T)
{
    __shared__ unsigned long long Ad[2][16][PA];
    __shared__ float Ws[2][16][PW];

    const int tid = threadIdx.x;
    const int bx  = blockIdx.x;
    const int m0 = (bx >> 6) << 6;
    const int n0 = (bx & 63) << 6;

    const int li = tid >> 2;
    const int lk = (tid & 3) << 2;
    const int ty = tid >> 4;
    const int tx = tid & 15;

    const float* wrow = W + (size_t)(n0 + li) * 1024 + lk;
    const int jj = (n0 >> 2) + tx;

    float cstate[4] = {0.f, 0.f, 0.f, 0.f};

    for (int t = 0; t < T; ++t) {
        const float* hbase = (t == 0) ? g_zero : h_all + (size_t)(t - 1) * BB * 1024;
        const float* arow = hbase + (size_t)(m0 + li) * 1024 + lk;

        float4 a_reg = ldcg4(arow);
        float4 w_reg = ldcg4(wrow);
        STORE_TILE(0);
        __syncthreads();

        unsigned long long acc[4][2];
#pragma unroll
        for (int r = 0; r < 4; ++r) { acc[r][0] = 0ull; acc[r][1] = 0ull; }

        for (int kt = 0; kt < 64; ++kt) {
            const int cur = kt & 1;
            if (kt + 1 < 64) {
                a_reg = ldcg4(arow + (size_t)(kt + 1) * 16);
                w_reg = ldcg4(wrow + (size_t)(kt + 1) * 16);
            }
            COMPUTE_TILE(cur);
            if (kt + 1 < 64) STORE_TILE(cur ^ 1);
            __syncthreads();
        }

        const float* gxt = gx + (size_t)t * BB * 4096;
        float* ht = h_all + (size_t)t * BB * 1024;
#pragma unroll
        for (int r = 0; r < 4; ++r) {
            const int row = m0 + (ty << 2) + r;
            float4 gv = ldcg4(gxt + (size_t)row * 4096 + n0 + (tx << 2));
            float2 v0 = upk2(acc[r][0]);
            float2 v1 = upk2(acc[r][1]);
            float gi = sigm(v0.x + gv.x);
            float gf = sigm(v0.y + gv.y);
            float gg = tanhf(v1.x + gv.z);
            float go = sigm(v1.y + gv.w);
            float c = gf * cstate[r] + gi * gg;
            cstate[r] = c;
            ht[(size_t)row * 1024 + jj] = go * tanhf(c);
        }

        grid_barrier();
    }
}

// ---------------- one-time weight permute / convert ----------------
__global__ void permute_w(const float* __restrict__ in, float* __restrict__ out, int ldk)
{
    int ro = blockIdx.x;
    int j = ro >> 2, g = ro & 3;
    const float* src = in + (size_t)(g * 1024 + j) * ldk;
    float* dst = out + (size_t)ro * ldk;
    for (int k = threadIdx.x * 4; k < ldk; k += blockDim.x * 4)
        *(float4*)(dst + k) = __ldcg((const float4*)(src + k));
}

// fp32 [N][ldk] -> bf16 hi/lo [N][K] (optionally gate-permuted rows)
__global__ void convert_w(const float* __restrict__ in,
                          __nv_bfloat16* __restrict__ hi, __nv_bfloat16* __restrict__ lo,
                          int ldk, int K, int doperm)
{
    int ro = blockIdx.x;
    int sr = doperm ? ((ro & 3) * 1024 + (ro >> 2)) : ro;
    const float* s = in + (size_t)sr * ldk;
    for (int k = threadIdx.x * 4; k < K; k += blockDim.x * 4) {
        float4 v = __ldcg((const float4*)(s + k));
        uint32_t hp0, lp0, hp1, lp1;
        split2(v.x, v.y, hp0, lp0);
        split2(v.z, v.w, hp1, lp1);
        *(uint2*)(hi + (size_t)ro * K + k) = make_uint2(hp0, hp1);
        *(uint2*)(lo + (size_t)ro * K + k) = make_uint2(lp0, lp1);
    }
}

__global__ void addperm(const float* __restrict__ a, const float* __restrict__ b,
                        float* __restrict__ o)
{
    int i = blockIdx.x * blockDim.x + threadIdx.x;
    int j = i >> 2, g = i & 3;
    int s = g * 1024 + j;
    o[i] = a[s] + b[s];
}

// ---------------- host ----------------
extern "C" void kernel_launch(void* const* d_in, const int* in_sizes, int n_in,
                              void* d_out, int out_size)
{
    const float* z      = (const float*)d_in[0];
    const float* x      = (const float*)d_in[1];
    const float* fcz_w  = (const float*)d_in[2];
    const float* fcz_b  = (const float*)d_in[3];
    const float* c_wih  = (const float*)d_in[4];
    const float* c_whh  = (const float*)d_in[5];
    const float* c_bih  = (const float*)d_in[6];
    const float* c_bhh  = (const float*)d_in[7];
    const float* fcc_w  = (const float*)d_in[8];
    const float* fcc_b  = (const float*)d_in[9];
    const float* d0_wih = (const float*)d_in[10];
    const float* d0_whh = (const float*)d_in[11];
    const float* d0_bih = (const float*)d_in[12];
    const float* d0_bhh = (const float*)d_in[13];
    const float* d1_wih = (const float*)d_in[14];
    const float* d1_whh = (const float*)d_in[15];
    const float* d1_bih = (const float*)d_in[16];
    const float* d1_bhh = (const float*)d_in[17];
    const float* out_w  = (const float*)d_in[18];
    const float* out_b  = (const float*)d_in[19];
    float* out = (float*)d_out;

    float *cin, *gxc, *condh, *emb, *gxe, *gx, *h0, *h1;
    float *cwih_p, *cwhh_p, *d0wih_p, *d0whh_p, *d1whh_p, *bsum_p;
    __nv_bfloat16 *d0wih_hi, *d0wih_lo, *d1wih_hi, *d1wih_lo, *outw_hi, *outw_lo;
    cudaGetSymbolAddress((void**)&cin,      g_cin);
    cudaGetSymbolAddress((void**)&gxc,      g_gxc);
    cudaGetSymbolAddress((void**)&condh,    g_condh);
    cudaGetSymbolAddress((void**)&emb,      g_emb);
    cudaGetSymbolAddress((void**)&gxe,      g_gxe);
    cudaGetSymbolAddress((void**)&gx,       g_gx);
    cudaGetSymbolAddress((void**)&h0,       g_h0);
    cudaGetSymbolAddress((void**)&h1,       g_h1);
    cudaGetSymbolAddress((void**)&cwih_p,   g_cwih_p);
    cudaGetSymbolAddress((void**)&cwhh_p,   g_cwhh_p);
    cudaGetSymbolAddress((void**)&d0wih_p,  g_d0wih_p);
    cudaGetSymbolAddress((void**)&d0whh_p,  g_d0whh_p);
    cudaGetSymbolAddress((void**)&d1whh_p,  g_d1whh_p);
    cudaGetSymbolAddress((void**)&bsum_p,   g_bsum_p);
    cudaGetSymbolAddress((void**)&d0wih_hi, g_d0wih_hi);
    cudaGetSymbolAddress((void**)&d0wih_lo, g_d0wih_lo);
    cudaGetSymbolAddress((void**)&d1wih_hi, g_d1wih_hi);
    cudaGetSymbolAddress((void**)&d1wih_lo, g_d1wih_lo);
    cudaGetSymbolAddress((void**)&outw_hi,  g_outw_hi);
    cudaGetSymbolAddress((void**)&outw_lo,  g_outw_lo);

    cudaFuncSetAttribute(gemm_mma, cudaFuncAttributeMaxDynamicSharedMemorySize, 2 * MST);

    dim3 blk(256);

    // one-time permutes / converts
    permute_w<<<4096, 128>>>(c_wih,  cwih_p,  HC);
    permute_w<<<4096, 128>>>(c_whh,  cwhh_p,  HC);
    permute_w<<<4096, 128>>>(d0_wih, d0wih_p, VV + EE);   // fp32 kept for gxe slice
    permute_w<<<4096, 128>>>(d0_whh, d0whh_p, HD);
    permute_w<<<4096, 128>>>(d1_whh, d1whh_p, HD);
    convert_w<<<4096, 256>>>(d0_wih, d0wih_hi, d0wih_lo, VV + EE, VV, 1);
    convert_w<<<4096, 256>>>(d1_wih, d1wih_hi, d1wih_lo, HD, HD, 1);
    convert_w<<<1024, 256>>>(out_w,  outw_hi,  outw_lo,  HD, HD, 0);
    addperm<<<16, 256>>>(c_bih,  c_bhh,  bsum_p);
    addperm<<<16, 256>>>(d0_bih, d0_bhh, bsum_p + 4096);
    addperm<<<16, 256>>>(d1_bih, d1_bhh, bsum_p + 8192);

    // ---- conductor (FFMA2 path; small) ----
    gemm_nt<<<dim3(HC / 64, (SSEQ * BB) / 64), blk>>>(
        z, fcz_w, fcz_b, nullptr, cin, SSEQ * BB, HC, ZZ, ZZ, 1, 0, 0, 0);
    gemm_nt<<<dim3(4 * HC / 64, (SSEQ * BB) / 64), blk>>>(
        cin, cwih_p, bsum_p, nullptr, gxc, SSEQ * BB, 4 * HC, HC, HC, 0, 0, 0, 0);
    lstm_recurrence<<<NBLK, blk>>>(cwhh_p, gxc, condh, SSEQ);
    gemm_nt<<<dim3(EE / 64, (SSEQ * BB) / 64), blk>>>(
        condh, fcc_w, fcc_b, nullptr, emb, SSEQ * BB, EE, HC, HC, 0, 0, 0, 1);
    gemm_nt<<<dim3(4 * HD / 64, (SSEQ * BB) / 64), blk>>>(
        emb, d0wih_p + VV, bsum_p + 4096, nullptr, gxe,
        SSEQ * BB, 4 * HD, EE, VV + EE, 0, 0, 0, 0);

    // ---- decoder layer 0: gx0 = prev_x @ W^T + gxe (HMMA) ----
    gemm_mma<<<dim3(4 * HD / 128, (TT * BB) / 128), blk, 2 * MST>>>(
        x, d0wih_hi, d0wih_lo, nullptr, gxe, gx, VV, 4 * HD, 2, 0);
    lstm_recurrence<<<NBLK, blk>>>(d0whh_p, gx, h0, TT);

    // ---- decoder layer 1: gx1 = h0 @ W^T + bias (HMMA) ----
    gemm_mma<<<dim3(4 * HD / 128, (TT * BB) / 128), blk, 2 * MST>>>(
        h0, d1wih_hi, d1wih_lo, bsum_p + 8192, nullptr, gx, HD, 4 * HD, 0, 0);
    lstm_recurrence<<<NBLK, blk>>>(d1whh_p, gx, h1, TT);

    // ---- output projection (HMMA, time-major -> [B,T,V]) ----
    gemm_mma<<<dim3(VV / 128, (TT * BB) / 128), blk, 2 * MST>>>(
        h1, outw_hi, outw_lo, out_b, nullptr, out, HD, VV, 0, 1);
}

// round 10
// speedup vs baseline: 2.7648x; 1.6058x over previous
#include <cuda_runtime.h>
#include <cuda_bf16.h>
#include <cstdint>

#define BB 128
#define SSEQ 16
#define TT 256
#define ZZ 512
#define HC 1024
#define EE 512
#define HD 1024
#define VV 1024
#define NBLK 128

// ---------------- scratch (device globals; zero-init at module load) ----------------
__device__ float g_zero[BB * HD];                       // never written: stays zero
__device__ float g_cin[SSEQ * BB * HC];
__device__ float g_gxc[SSEQ * BB * 4 * HC];             // perm gate order
__device__ float g_condh[SSEQ * BB * HC];
__device__ float g_emb[SSEQ * BB * EE];
__device__ float g_gxe[SSEQ * BB * 4 * HD];             // perm
__device__ float g_gx[TT * BB * 4 * HD];                // perm
__device__ float g_h0[TT * BB * HD];
__device__ float g_h1[TT * BB * HD];
__device__ float g_bsum_p[3 * 4 * HD];
// bf16 h history (hi/lo split), shared across the three recurrences (serial launches)
__device__ __align__(16) __nv_bfloat16 g_hhi[TT * BB * HD];
__device__ __align__(16) __nv_bfloat16 g_hlo[TT * BB * HD];
// bf16 hi/lo split weights (mma consumers)
__device__ __align__(16) __nv_bfloat16 g_cwih_hi[4 * HC * HC];
__device__ __align__(16) __nv_bfloat16 g_cwih_lo[4 * HC * HC];
__device__ __align__(16) __nv_bfloat16 g_cwhh_hi[4 * HC * HC];
__device__ __align__(16) __nv_bfloat16 g_cwhh_lo[4 * HC * HC];
__device__ __align__(16) __nv_bfloat16 g_d0wih_hi[4 * HD * VV];
__device__ __align__(16) __nv_bfloat16 g_d0wih_lo[4 * HD * VV];
__device__ __align__(16) __nv_bfloat16 g_d0wihE_hi[4 * HD * EE];
__device__ __align__(16) __nv_bfloat16 g_d0wihE_lo[4 * HD * EE];
__device__ __align__(16) __nv_bfloat16 g_d0whh_hi[4 * HD * HD];
__device__ __align__(16) __nv_bfloat16 g_d0whh_lo[4 * HD * HD];
__device__ __align__(16) __nv_bfloat16 g_d1wih_hi[4 * HD * HD];
__device__ __align__(16) __nv_bfloat16 g_d1wih_lo[4 * HD * HD];
__device__ __align__(16) __nv_bfloat16 g_d1whh_hi[4 * HD * HD];
__device__ __align__(16) __nv_bfloat16 g_d1whh_lo[4 * HD * HD];
__device__ __align__(16) __nv_bfloat16 g_outw_hi[VV * HD];
__device__ __align__(16) __nv_bfloat16 g_outw_lo[VV * HD];

// grid-barrier state
__device__ volatile unsigned int g_bar_gen;
__device__ unsigned int g_bar_cnt;

// ---------------- helpers ----------------
__device__ __forceinline__ unsigned long long ffma2(unsigned long long a,
                                                    unsigned long long b,
                                                    unsigned long long c) {
    unsigned long long d;
    asm("fma.rn.f32x2 %0, %1, %2, %3;" : "=l"(d) : "l"(a), "l"(b), "l"(c));
    return d;
}
__device__ __forceinline__ unsigned long long pk2(float x, float y) {
    unsigned long long r;
    asm("mov.b64 %0, {%1, %2};" : "=l"(r) : "f"(x), "f"(y));
    return r;
}
__device__ __forceinline__ float2 upk2(unsigned long long v) {
    float2 d;
    asm("mov.b64 {%0, %1}, %2;" : "=f"(d.x), "=f"(d.y) : "l"(v));
    return d;
}
__device__ __forceinline__ float4 ldcg4(const float* p) {
    return __ldcg((const float4*)(p));
}
__device__ __forceinline__ float sigm(float x) { return 1.f / (1.f + expf(-x)); }

__device__ __forceinline__ uint32_t smem_u32(const void* p) {
    uint32_t a;
    asm("{ .reg .u64 t; cvta.to.shared.u64 t, %1; cvt.u32.u64 %0, t; }" : "=r"(a) : "l"(p));
    return a;
}
__device__ __forceinline__ uint32_t pack_bf16(__nv_bfloat16 a, __nv_bfloat16 b) {
    return (uint32_t)__bfloat16_as_ushort(a) | ((uint32_t)__bfloat16_as_ushort(b) << 16);
}
__device__ __forceinline__ void split2(float x, float y, uint32_t& hp, uint32_t& lp) {
    __nv_bfloat16 hx = __float2bfloat16(x), hy = __float2bfloat16(y);
    __nv_bfloat16 lx = __float2bfloat16(x - __bfloat162float(hx));
    __nv_bfloat16 ly = __float2bfloat16(y - __bfloat162float(hy));
    hp = pack_bf16(hx, hy);
    lp = pack_bf16(lx, ly);
}

// ---------------- mma.sync (HMMA) primitives — baseline PTX, legal on compute_103 ----------------
#define MMA_BF16(d, a, b0, b1)                                                  \
    asm volatile("mma.sync.aligned.m16n8k16.row.col.f32.bf16.bf16.f32 "         \
        "{%0,%1,%2,%3}, {%4,%5,%6,%7}, {%8,%9}, {%0,%1,%2,%3};"                 \
        : "+f"((d)[0]), "+f"((d)[1]), "+f"((d)[2]), "+f"((d)[3])                \
        : "r"((a)[0]), "r"((a)[1]), "r"((a)[2]), "r"((a)[3]), "r"(b0), "r"(b1))

#define LDMX4(r, addr)                                                          \
    asm volatile("ldmatrix.sync.aligned.m8n8.x4.shared.b16 {%0,%1,%2,%3}, [%4];" \
        : "=r"((r)[0]), "=r"((r)[1]), "=r"((r)[2]), "=r"((r)[3]) : "r"(addr))

// ---------------- HMMA GEMM: C[M,N] = gather(A)[M,K] * W[N,K]^T (+bias)(+Cin) ----------------
// 128x128 tile per CTA, 8 warps (2 m x 4 n), warp tile 64x32, K-chunk 32.
// A fp32 split to bf16 hi/lo in transit; W pre-split. 3 mmas per (frag,k16): hh, hl, lh.
// Rows of 64B (32 bf16); 16B-chunk XOR swizzle: phys_chunk = logical ^ (row & 3).
// amode: 0 = A row m; 2 = prev-x gather (m=t*BB+b reads x row b*TT+t-1; zeros at t==0).
// Cin (if set): row (t>>4)*BB+b (embedding addend).  cmode: 0 = row m; 1 = row (b*TT+t).
#define MST 32768
__global__ __launch_bounds__(256, 1)
void gemm_mma(const float* __restrict__ A,
              const __nv_bfloat16* __restrict__ Whi,
              const __nv_bfloat16* __restrict__ Wlo,
              const float* __restrict__ bias, const float* __restrict__ Cin,
              float* __restrict__ C,
              int K, int N, int amode, int cmode)
{
    extern __shared__ char sm[];
    const uint32_t sb = smem_u32(sm);
    const int tid = threadIdx.x;
    const int lane = tid & 31;
    const int wid = tid >> 5;
    const int warp_m = wid & 1;
    const int warp_n = wid >> 1;
    const int m0 = blockIdx.y << 7;
    const int n0 = blockIdx.x << 7;

    const int lrow = tid >> 1;
    const int half = tid & 1;

    const float* arow;
    {
        int m = m0 + lrow;
        if (amode == 0) {
            arow = A + (size_t)m * K;
        } else {
            int t = m >> 7, b = m & 127;
            arow = (t == 0) ? g_zero : A + ((size_t)b * TT + (t - 1)) * 1024;
        }
    }
    const uint4* whrow = (const uint4*)(Whi + (size_t)(n0 + lrow) * K);
    const uint4* wlrow = (const uint4*)(Wlo + (size_t)(n0 + lrow) * K);

    const uint32_t sst0 = (uint32_t)lrow * 64u + (uint32_t)(((half * 2)     ^ (lrow & 3)) << 4);
    const uint32_t sst1 = (uint32_t)lrow * 64u + (uint32_t)(((half * 2 + 1) ^ (lrow & 3)) << 4);

    uint32_t a_addr[4][2], b_addr[2][2];
    {
        int ar = warp_m * 64 + (lane & 7) + (((lane >> 3) & 1) << 3);
        int akh = lane >> 4;
        int br = warp_n * 32 + (lane & 7) + ((lane >> 4) << 3);
        int bkh = (lane >> 3) & 1;
#pragma unroll
        for (int mi = 0; mi < 4; ++mi)
#pragma unroll
            for (int kk = 0; kk < 2; ++kk) {
                int row = ar + mi * 16;
                a_addr[mi][kk] = sb + (uint32_t)row * 64u
                               + (uint32_t)((((kk << 1) | akh) ^ (row & 3)) << 4);
            }
#pragma unroll
        for (int ng = 0; ng < 2; ++ng)
#pragma unroll
            for (int kk = 0; kk < 2; ++kk) {
                int row = br + ng * 16;
                b_addr[ng][kk] = sb + 16384u + (uint32_t)row * 64u
                               + (uint32_t)((((kk << 1) | bkh) ^ (row & 3)) << 4);
            }
    }

    float acc[4][4][4];
#pragma unroll
    for (int mi = 0; mi < 4; ++mi)
#pragma unroll
        for (int nf = 0; nf < 4; ++nf)
#pragma unroll
            for (int q = 0; q < 4; ++q) acc[mi][nf][q] = 0.f;

    const int NC = K >> 5;
    float4 pa[4];
    uint4 pwh[2], pwl[2];

#pragma unroll
    for (int i = 0; i < 4; ++i) pa[i] = ldcg4(arow + half * 16 + i * 4);
#pragma unroll
    for (int j = 0; j < 2; ++j) {
        pwh[j] = __ldcg(whrow + half * 2 + j);
        pwl[j] = __ldcg(wlrow + half * 2 + j);
    }
    {
        uint32_t h0a, l0a, h0b, l0b, h1a, l1a, h1b, l1b;
        split2(pa[0].x, pa[0].y, h0a, l0a); split2(pa[0].z, pa[0].w, h0b, l0b);
        split2(pa[1].x, pa[1].y, h1a, l1a); split2(pa[1].z, pa[1].w, h1b, l1b);
        *(uint4*)(sm + sst0)         = make_uint4(h0a, h0b, h1a, h1b);
        *(uint4*)(sm + 8192 + sst0)  = make_uint4(l0a, l0b, l1a, l1b);
        split2(pa[2].x, pa[2].y, h0a, l0a); split2(pa[2].z, pa[2].w, h0b, l0b);
        split2(pa[3].x, pa[3].y, h1a, l1a); split2(pa[3].z, pa[3].w, h1b, l1b);
        *(uint4*)(sm + sst1)         = make_uint4(h0a, h0b, h1a, h1b);
        *(uint4*)(sm + 8192 + sst1)  = make_uint4(l0a, l0b, l1a, l1b);
        *(uint4*)(sm + 16384 + sst0) = pwh[0];
        *(uint4*)(sm + 16384 + sst1) = pwh[1];
        *(uint4*)(sm + 24576 + sst0) = pwl[0];
        *(uint4*)(sm + 24576 + sst1) = pwl[1];
    }
    __syncthreads();

    for (int c = 0; c < NC; ++c) {
        const int cur = c & 1;
        const uint32_t soff = (uint32_t)cur * MST;
        if (c + 1 < NC) {
#pragma unroll
            for (int i = 0; i < 4; ++i)
                pa[i] = ldcg4(arow + (c + 1) * 32 + half * 16 + i * 4);
#pragma unroll
            for (int j = 0; j < 2; ++j) {
                pwh[j] = __ldcg(whrow + (c + 1) * 4 + half * 2 + j);
                pwl[j] = __ldcg(wlrow + (c + 1) * 4 + half * 2 + j);
            }
        }

#pragma unroll
        for (int kk = 0; kk < 2; ++kk) {
            uint32_t ah[4][4], al[4][4], bh[2][4], bl[2][4];
#pragma unroll
            for (int mi = 0; mi < 4; ++mi) {
                LDMX4(ah[mi], a_addr[mi][kk] + soff);
                LDMX4(al[mi], a_addr[mi][kk] + soff + 8192u);
            }
#pragma unroll
            for (int ng = 0; ng < 2; ++ng) {
                LDMX4(bh[ng], b_addr[ng][kk] + soff);
                LDMX4(bl[ng], b_addr[ng][kk] + soff + 8192u);
            }
#pragma unroll
            for (int mi = 0; mi < 4; ++mi) {
#pragma unroll
                for (int nf = 0; nf < 4; ++nf) {
                    const int ng = nf >> 1;
                    const int p = (nf & 1) << 1;
                    MMA_BF16(acc[mi][nf], ah[mi], bh[ng][p], bh[ng][p + 1]);
                    MMA_BF16(acc[mi][nf], ah[mi], bl[ng][p], bl[ng][p + 1]);
                    MMA_BF16(acc[mi][nf], al[mi], bh[ng][p], bh[ng][p + 1]);
                }
            }
        }

        if (c + 1 < NC) {
            char* d = sm + (cur ^ 1) * MST;
            uint32_t h0a, l0a, h0b, l0b, h1a, l1a, h1b, l1b;
            split2(pa[0].x, pa[0].y, h0a, l0a); split2(pa[0].z, pa[0].w, h0b, l0b);
            split2(pa[1].x, pa[1].y, h1a, l1a); split2(pa[1].z, pa[1].w, h1b, l1b);
            *(uint4*)(d + sst0)         = make_uint4(h0a, h0b, h1a, h1b);
            *(uint4*)(d + 8192 + sst0)  = make_uint4(l0a, l0b, l1a, l1b);
            split2(pa[2].x, pa[2].y, h0a, l0a); split2(pa[2].z, pa[2].w, h0b, l0b);
            split2(pa[3].x, pa[3].y, h1a, l1a); split2(pa[3].z, pa[3].w, h1b, l1b);
            *(uint4*)(d + sst1)         = make_uint4(h0a, h0b, h1a, h1b);
            *(uint4*)(d + 8192 + sst1)  = make_uint4(l0a, l0b, l1a, l1b);
            *(uint4*)(d + 16384 + sst0) = pwh[0];
            *(uint4*)(d + 16384 + sst1) = pwh[1];
            *(uint4*)(d + 24576 + sst0) = pwl[0];
            *(uint4*)(d + 24576 + sst1) = pwl[1];
        }
        __syncthreads();
    }

    const int grp = lane >> 2;
    const int cl  = (lane & 3) << 1;
#pragma unroll
    for (int mi = 0; mi < 4; ++mi) {
#pragma unroll
        for (int h = 0; h < 2; ++h) {
            const int row = m0 + warp_m * 64 + mi * 16 + grp + h * 8;
            size_t coff;
            if (cmode == 0) {
                coff = (size_t)row * N;
            } else {
                int t = row >> 7, b = row & 127;
                coff = ((size_t)b * TT + t) * N;
            }
            size_t cinoff = 0;
            if (Cin) {
                int cr = ((row >> 11) << 7) + (row & 127);
                cinoff = (size_t)cr * N;
            }
#pragma unroll
            for (int nf = 0; nf < 4; ++nf) {
                const int col = n0 + warp_n * 32 + nf * 8 + cl;
                float2 v = make_float2(acc[mi][nf][h * 2], acc[mi][nf][h * 2 + 1]);
                if (bias) { v.x += bias[col]; v.y += bias[col + 1]; }
                if (Cin)  {
                    float2 ci = *(const float2*)(Cin + cinoff + col);
                    v.x += ci.x; v.y += ci.y;
                }
                *(float2*)(C + coff + col) = v;
            }
        }
    }
}

// ---------------- grid barrier (all NBLK blocks co-resident) ----------------
__device__ __forceinline__ void grid_barrier()
{
    __syncthreads();
    __threadfence();
    if (threadIdx.x == 0) {
        unsigned int gen = g_bar_gen;
        if (atomicAdd(&g_bar_cnt, 1u) == NBLK - 1u) {
            g_bar_cnt = 0u;
            __threadfence();
            g_bar_gen = gen + 1u;
        } else {
            while (g_bar_gen == gen) { __nanosleep(64); }
        }
    }
    __syncthreads();
}

// ---------------- persistent HMMA LSTM recurrence ----------------
// 128 CTAs: tile 64 rows (m0 = (bx>>6)*64) x 64 perm-cols (n0 = (bx&63)*64), K=1024.
// h kept as bf16 hi/lo pairs (split exactly in the cell epilogue); W_hh pre-split.
// Stage (16KB): [Ahi 4K][Alo 4K][Whi 4K][Wlo 4K]; 2 stages; gates 64x72 fp32 after.
// Warp layout: 8 warps = 2 m (32 rows) x 4 n (16 cols). 3 mmas per (frag,k16).
#define RST 16384
#define RSMEM (2 * RST + 64 * 72 * 4)
__global__ __launch_bounds__(256, 1)
void lstm_rec_mma(const __nv_bfloat16* __restrict__ Whi,
                  const __nv_bfloat16* __restrict__ Wlo,
                  const float* __restrict__ gx,
                  float* __restrict__ hf,
                  __nv_bfloat16* __restrict__ hhi,
                  __nv_bfloat16* __restrict__ hlo,
                  int T)
{
    extern __shared__ char sm[];
    const uint32_t sb = smem_u32(sm);
    float* gsm = (float*)(sm + 2 * RST);
    const int tid = threadIdx.x;
    const int lane = tid & 31;
    const int wid = tid >> 5;
    const int warp_m = wid & 1;
    const int warp_n = wid >> 1;
    const int bx = blockIdx.x;
    const int m0 = (bx >> 6) << 6;          // 0 or 64
    const int n0 = (bx & 63) << 6;          // 0..4032 (perm cols)

    // loader: thread -> (row 0..63, 16B quad 0..3); swizzle chunk ^= row&3
    const int lrow = tid >> 2;
    const int quad = tid & 3;
    const uint32_t sst = (uint32_t)lrow * 64u + (uint32_t)((quad ^ (lrow & 3)) << 4);

    const uint4* whr = (const uint4*)(Whi + (size_t)(n0 + lrow) * 1024) + quad;
    const uint4* wlr = (const uint4*)(Wlo + (size_t)(n0 + lrow) * 1024) + quad;

    // ldmatrix addresses (stage 0; +soff per chunk). A: rows 0..63 region base 0 (hi)/4096 (lo).
    // B(W): rows 0..63 region base 8192 (hi)/12288 (lo).
    uint32_t a_addr[2][2], b_addr[2];
    {
        int ar = warp_m * 32 + (lane & 7) + (((lane >> 3) & 1) << 3);
        int akh = lane >> 4;
#pragma unroll
        for (int mi = 0; mi < 2; ++mi)
#pragma unroll
            for (int kk = 0; kk < 2; ++kk) {
                int row = ar + mi * 16;
                a_addr[mi][kk] = sb + (uint32_t)row * 64u
                               + (uint32_t)((((kk << 1) | akh) ^ (row & 3)) << 4);
            }
        int br = warp_n * 16 + (lane & 7) + ((lane >> 4) << 3);
        int bkh = (lane >> 3) & 1;
#pragma unroll
        for (int kk = 0; kk < 2; ++kk)
            b_addr[kk] = sb + 8192u + (uint32_t)br * 64u
                       + (uint32_t)((((kk << 1) | bkh) ^ (br & 3)) << 4);
    }

    const int grp = lane >> 2;
    const int cl  = (lane & 3) << 1;

    float cstate[4] = {0.f, 0.f, 0.f, 0.f};

    for (int t = 0; t < T; ++t) {
        float acc[2][2][4];
#pragma unroll
        for (int mi = 0; mi < 2; ++mi)
#pragma unroll
            for (int nf = 0; nf < 2; ++nf)
#pragma unroll
                for (int q = 0; q < 4; ++q) acc[mi][nf][q] = 0.f;

        if (t > 0) {
            const uint4* ahr = (const uint4*)(hhi + (size_t)(t - 1) * BB * 1024
                                              + (size_t)(m0 + lrow) * 1024) + quad;
            const uint4* alr = (const uint4*)(hlo + (size_t)(t - 1) * BB * 1024
                                              + (size_t)(m0 + lrow) * 1024) + quad;
            uint4 vah = __ldcg(ahr);
            uint4 val_ = __ldcg(alr);
            uint4 vwh = __ldg(whr);
            uint4 vwl = __ldg(wlr);
            *(uint4*)(sm + sst)          = vah;
            *(uint4*)(sm + 4096 + sst)   = val_;
            *(uint4*)(sm + 8192 + sst)   = vwh;
            *(uint4*)(sm + 12288 + sst)  = vwl;
            __syncthreads();

            for (int c = 0; c < 32; ++c) {
                const uint32_t soff = (uint32_t)(c & 1) * RST;
                if (c + 1 < 32) {
                    vah = __ldcg(ahr + (c + 1) * 4);
                    val_ = __ldcg(alr + (c + 1) * 4);
                    vwh = __ldg(whr + (c + 1) * 4);
                    vwl = __ldg(wlr + (c + 1) * 4);
                }
#pragma unroll
                for (int kk = 0; kk < 2; ++kk) {
                    uint32_t ah[2][4], al[2][4], bh[4], bl[4];
                    LDMX4(ah[0], a_addr[0][kk] + soff);
                    LDMX4(ah[1], a_addr[1][kk] + soff);
                    LDMX4(al[0], a_addr[0][kk] + soff + 4096u);
                    LDMX4(al[1], a_addr[1][kk] + soff + 4096u);
                    LDMX4(bh, b_addr[kk] + soff);
                    LDMX4(bl, b_addr[kk] + soff + 4096u);
#pragma unroll
                    for (int mi = 0; mi < 2; ++mi) {
#pragma unroll
                        for (int nf = 0; nf < 2; ++nf) {
                            const int p = nf << 1;
                            MMA_BF16(acc[mi][nf], ah[mi], bh[p], bh[p + 1]);
                            MMA_BF16(acc[mi][nf], ah[mi], bl[p], bl[p + 1]);
                            MMA_BF16(acc[mi][nf], al[mi], bh[p], bh[p + 1]);
                        }
                    }
                }
                if (c + 1 < 32) {
                    char* d = sm + ((c & 1) ^ 1) * RST;
                    *(uint4*)(d + sst)         = vah;
                    *(uint4*)(d + 4096 + sst)  = val_;
                    *(uint4*)(d + 8192 + sst)  = vwh;
                    *(uint4*)(d + 12288 + sst) = vwl;
                }
                __syncthreads();
            }
        }

        // gate fragments -> smem (64 x 72 fp32)
#pragma unroll
        for (int mi = 0; mi < 2; ++mi)
#pragma unroll
            for (int h2 = 0; h2 < 2; ++h2) {
                const int row = warp_m * 32 + mi * 16 + grp + h2 * 8;
#pragma unroll
                for (int nf = 0; nf < 2; ++nf) {
                    const int col = warp_n * 16 + nf * 8 + cl;
                    gsm[row * 72 + col]     = acc[mi][nf][h2 * 2];
                    gsm[row * 72 + col + 1] = acc[mi][nf][h2 * 2 + 1];
                }
            }
        __syncthreads();

        // fused cell: gates = gsm + gx[t]; c in regs; write h {fp32, hi, lo}
        const float* gxt = gx + (size_t)t * BB * 4096;
#pragma unroll
        for (int it = 0; it < 4; ++it) {
            const int idx = it * 256 + tid;
            const int crow = idx >> 4;
            const int cj = idx & 15;
            const int rg = m0 + crow;
            const int jg = (n0 >> 2) + cj;
            float4 ga = *(const float4*)(gsm + crow * 72 + cj * 4);
            float4 gv = ldcg4(gxt + (size_t)rg * 4096 + n0 + cj * 4);
            float gi = sigm(ga.x + gv.x);
            float gf = sigm(ga.y + gv.y);
            float gg = tanhf(ga.z + gv.z);
            float go = sigm(ga.w + gv.w);
            float cc = gf * cstate[it] + gi * gg;
            cstate[it] = cc;
            float hv = go * tanhf(cc);
            const size_t off = (size_t)t * BB * 1024 + (size_t)rg * 1024 + jg;
            hf[off] = hv;
            __nv_bfloat16 hh = __float2bfloat16(hv);
            hhi[off] = hh;
            hlo[off] = __float2bfloat16(hv - __bfloat162float(hh));
        }

        grid_barrier();
    }
}

// ---------------- FFMA2 tile macros (remaining small GEMMs) ----------------
#define PA 66
#define PW 68
#define STORE_TILE(buf)                                            \
    do {                                                           \
        Ad[buf][lk + 0][li] = pk2(a_reg.x, a_reg.x);               \
        Ad[buf][lk + 1][li] = pk2(a_reg.y, a_reg.y);               \
        Ad[buf][lk + 2][li] = pk2(a_reg.z, a_reg.z);               \
        Ad[buf][lk + 3][li] = pk2(a_reg.w, a_reg.w);               \
        Ws[buf][lk + 0][li] = w_reg.x;                             \
        Ws[buf][lk + 1][li] = w_reg.y;                             \
        Ws[buf][lk + 2][li] = w_reg.z;                             \
        Ws[buf][lk + 3][li] = w_reg.w;                             \
    } while (0)

#define COMPUTE_TILE(buf)                                                     \
    do {                                                                      \
        _Pragma("unroll")                                                     \
        for (int k = 0; k < 16; ++k) {                                        \
            ulonglong2 a01 = *(const ulonglong2*)&Ad[buf][k][(ty << 2)];      \
            ulonglong2 a23 = *(const ulonglong2*)&Ad[buf][k][(ty << 2) + 2];  \
            ulonglong2 w01 = *(const ulonglong2*)&Ws[buf][k][(tx << 2)];      \
            acc[0][0] = ffma2(a01.x, w01.x, acc[0][0]);                       \
            acc[0][1] = ffma2(a01.x, w01.y, acc[0][1]);                       \
            acc[1][0] = ffma2(a01.y, w01.x, acc[1][0]);                       \
            acc[1][1] = ffma2(a01.y, w01.y, acc[1][1]);                       \
            acc[2][0] = ffma2(a23.x, w01.x, acc[2][0]);                       \
            acc[2][1] = ffma2(a23.x, w01.y, acc[2][1]);                       \
            acc[3][0] = ffma2(a23.y, w01.x, acc[3][0]);                       \
            acc[3][1] = ffma2(a23.y, w01.y, acc[3][1]);                       \
        }                                                                     \
    } while (0)

// amode: 0 = A row m; 1 = z-gather (m=s*BB+b reads z row b*SSEQ+s)
// act: 0 = none; 1 = tanh
__global__ __launch_bounds__(256, 2)
void gemm_nt(const float* __restrict__ A, const float* __restrict__ W,
             const float* __restrict__ bias, float* __restrict__ C,
             int M, int N, int K, int ldw, int amode, int act)
{
    __shared__ unsigned long long Ad[2][16][PA];
    __shared__ float Ws[2][16][PW];

    const int tid = threadIdx.x;
    const int m0 = blockIdx.y << 6;
    const int n0 = blockIdx.x << 6;

    const int li = tid >> 2;
    const int lk = (tid & 3) << 2;
    const int ty = tid >> 4;
    const int tx = tid & 15;

    const int m = m0 + li;
    const float* arow;
    if (amode == 0) {
        arow = A + (size_t)m * K;
    } else {
        int b = m & (BB - 1), s = m >> 7;
        arow = A + ((size_t)b * SSEQ + s) * K;
    }
    arow += lk;
    const float* wrow = W + (size_t)(n0 + li) * ldw + lk;

    const int nkt = K >> 4;
    float4 a_reg = ldcg4(arow);
    float4 w_reg = ldcg4(wrow);
    STORE_TILE(0);
    __syncthreads();

    unsigned long long acc[4][2];
#pragma unroll
    for (int r = 0; r < 4; ++r) { acc[r][0] = 0ull; acc[r][1] = 0ull; }

    for (int kt = 0; kt < nkt; ++kt) {
        const int cur = kt & 1;
        if (kt + 1 < nkt) {
            a_reg = ldcg4(arow + (size_t)(kt + 1) * 16);
            w_reg = ldcg4(wrow + (size_t)(kt + 1) * 16);
        }
        COMPUTE_TILE(cur);
        if (kt + 1 < nkt) STORE_TILE(cur ^ 1);
        __syncthreads();
    }

#pragma unroll
    for (int r = 0; r < 4; ++r) {
        const int row = m0 + (ty << 2) + r;
#pragma unroll
        for (int p = 0; p < 2; ++p) {
            const int col = n0 + (tx << 2) + (p << 1);
            float2 v = upk2(acc[r][p]);
            if (bias) { v.x += bias[col]; v.y += bias[col + 1]; }
            if (act)  { v.x = tanhf(v.x); v.y = tanhf(v.y); }
            *(float2*)(C + (size_t)row * N + col) = v;
        }
    }
}

// ---------------- one-time weight convert: fp32 -> bf16 hi/lo ----------------
// out rows ro (optionally gate-permuted source row), K cols starting at source col k0.
__global__ void convert_w(const float* __restrict__ in,
                          __nv_bfloat16* __restrict__ hi, __nv_bfloat16* __restrict__ lo,
                          int ldk, int K, int doperm, int k0)
{
    int ro = blockIdx.x;
    int sr = doperm ? ((ro & 3) * 1024 + (ro >> 2)) : ro;
    const float* s = in + (size_t)sr * ldk + k0;
    for (int k = threadIdx.x * 4; k < K; k += blockDim.x * 4) {
        float4 v = __ldcg((const float4*)(s + k));
        uint32_t hp0, lp0, hp1, lp1;
        split2(v.x, v.y, hp0, lp0);
        split2(v.z, v.w, hp1, lp1);
        *(uint2*)(hi + (size_t)ro * K + k) = make_uint2(hp0, hp1);
        *(uint2*)(lo + (size_t)ro * K + k) = make_uint2(lp0, lp1);
    }
}

__global__ void addperm(const float* __restrict__ a, const float* __restrict__ b,
                        float* __restrict__ o)
{
    int i = blockIdx.x * blockDim.x + threadIdx.x;
    int j = i >> 2, g = i & 3;
    int s = g * 1024 + j;
    o[i] = a[s] + b[s];
}

// ---------------- host ----------------
extern "C" void kernel_launch(void* const* d_in, const int* in_sizes, int n_in,
                              void* d_out, int out_size)
{
    const float* z      = (const float*)d_in[0];
    const float* x      = (const float*)d_in[1];
    const float* fcz_w  = (const float*)d_in[2];
    const float* fcz_b  = (const float*)d_in[3];
    const float* c_wih  = (const float*)d_in[4];
    const float* c_whh  = (const float*)d_in[5];
    const float* c_bih  = (const float*)d_in[6];
    const float* c_bhh  = (const float*)d_in[7];
    const float* fcc_w  = (const float*)d_in[8];
    const float* fcc_b  = (const float*)d_in[9];
    const float* d0_wih = (const float*)d_in[10];
    const float* d0_whh = (const float*)d_in[11];
    const float* d0_bih = (const float*)d_in[12];
    const float* d0_bhh = (const float*)d_in[13];
    const float* d1_wih = (const float*)d_in[14];
    const float* d1_whh = (const float*)d_in[15];
    const float* d1_bih = (const float*)d_in[16];
    const float* d1_bhh = (const float*)d_in[17];
    const float* out_w  = (const float*)d_in[18];
    const float* out_b  = (const float*)d_in[19];
    float* out = (float*)d_out;

    float *cin, *gxc, *condh, *emb, *gxe, *gx, *h0, *h1, *bsum_p;
    __nv_bfloat16 *hhi, *hlo;
    __nv_bfloat16 *cwih_hi, *cwih_lo, *cwhh_hi, *cwhh_lo;
    __nv_bfloat16 *d0wih_hi, *d0wih_lo, *d0wihE_hi, *d0wihE_lo, *d0whh_hi, *d0whh_lo;
    __nv_bfloat16 *d1wih_hi, *d1wih_lo, *d1whh_hi, *d1whh_lo, *outw_hi, *outw_lo;
    cudaGetSymbolAddress((void**)&cin,       g_cin);
    cudaGetSymbolAddress((void**)&gxc,       g_gxc);
    cudaGetSymbolAddress((void**)&condh,     g_condh);
    cudaGetSymbolAddress((void**)&emb,       g_emb);
    cudaGetSymbolAddress((void**)&gxe,       g_gxe);
    cudaGetSymbolAddress((void**)&gx,        g_gx);
    cudaGetSymbolAddress((void**)&h0,        g_h0);
    cudaGetSymbolAddress((void**)&h1,        g_h1);
    cudaGetSymbolAddress((void**)&bsum_p,    g_bsum_p);
    cudaGetSymbolAddress((void**)&hhi,       g_hhi);
    cudaGetSymbolAddress((void**)&hlo,       g_hlo);
    cudaGetSymbolAddress((void**)&cwih_hi,   g_cwih_hi);
    cudaGetSymbolAddress((void**)&cwih_lo,   g_cwih_lo);
    cudaGetSymbolAddress((void**)&cwhh_hi,   g_cwhh_hi);
    cudaGetSymbolAddress((void**)&cwhh_lo,   g_cwhh_lo);
    cudaGetSymbolAddress((void**)&d0wih_hi,  g_d0wih_hi);
    cudaGetSymbolAddress((void**)&d0wih_lo,  g_d0wih_lo);
    cudaGetSymbolAddress((void**)&d0wihE_hi, g_d0wihE_hi);
    cudaGetSymbolAddress((void**)&d0wihE_lo, g_d0wihE_lo);
    cudaGetSymbolAddress((void**)&d0whh_hi,  g_d0whh_hi);
    cudaGetSymbolAddress((void**)&d0whh_lo,  g_d0whh_lo);
    cudaGetSymbolAddress((void**)&d1wih_hi,  g_d1wih_hi);
    cudaGetSymbolAddress((void**)&d1wih_lo,  g_d1wih_lo);
    cudaGetSymbolAddress((void**)&d1whh_hi,  g_d1whh_hi);
    cudaGetSymbolAddress((void**)&d1whh_lo,  g_d1whh_lo);
    cudaGetSymbolAddress((void**)&outw_hi,   g_outw_hi);
    cudaGetSymbolAddress((void**)&outw_lo,   g_outw_lo);

    cudaFuncSetAttribute(gemm_mma, cudaFuncAttributeMaxDynamicSharedMemorySize, 2 * MST);
    cudaFuncSetAttribute(lstm_rec_mma, cudaFuncAttributeMaxDynamicSharedMemorySize, RSMEM);

    dim3 blk(256);

    // one-time converts (gate-permuted where consumed in perm order)
    convert_w<<<4096, 256>>>(c_wih,  cwih_hi,  cwih_lo,  HC, HC, 1, 0);
    convert_w<<<4096, 256>>>(c_whh,  cwhh_hi,  cwhh_lo,  HC, HC, 1, 0);
    convert_w<<<4096, 256>>>(d0_wih, d0wih_hi, d0wih_lo, VV + EE, VV, 1, 0);
    convert_w<<<4096, 256>>>(d0_wih, d0wihE_hi, d0wihE_lo, VV + EE, EE, 1, VV);
    convert_w<<<4096, 256>>>(d0_whh, d0whh_hi, d0whh_lo, HD, HD, 1, 0);
    convert_w<<<4096, 256>>>(d1_wih, d1wih_hi, d1wih_lo, HD, HD, 1, 0);
    convert_w<<<4096, 256>>>(d1_whh, d1whh_hi, d1whh_lo, HD, HD, 1, 0);
    convert_w<<<1024, 256>>>(out_w,  outw_hi,  outw_lo,  HD, HD, 0, 0);
    addperm<<<16, 256>>>(c_bih,  c_bhh,  bsum_p);
    addperm<<<16, 256>>>(d0_bih, d0_bhh, bsum_p + 4096);
    addperm<<<16, 256>>>(d1_bih, d1_bhh, bsum_p + 8192);

    // ---- conductor ----
    gemm_nt<<<dim3(HC / 64, (SSEQ * BB) / 64), blk>>>(
        z, fcz_w, fcz_b, cin, SSEQ * BB, HC, ZZ, ZZ, 1, 0);
    gemm_mma<<<dim3(4 * HC / 128, (SSEQ * BB) / 128), blk, 2 * MST>>>(
        cin, cwih_hi, cwih_lo, bsum_p, nullptr, gxc, HC, 4 * HC, 0, 0);
    lstm_rec_mma<<<NBLK, blk, RSMEM>>>(cwhh_hi, cwhh_lo, gxc, condh, hhi, hlo, SSEQ);
    gemm_nt<<<dim3(EE / 64, (SSEQ * BB) / 64), blk>>>(
        condh, fcc_w, fcc_b, emb, SSEQ * BB, EE, HC, HC, 0, 1);
    gemm_mma<<<dim3(4 * HD / 128, (SSEQ * BB) / 128), blk, 2 * MST>>>(
        emb, d0wihE_hi, d0wihE_lo, bsum_p + 4096, nullptr, gxe, EE, 4 * HD, 0, 0);

    // ---- decoder layer 0 ----
    gemm_mma<<<dim3(4 * HD / 128, (TT * BB) / 128), blk, 2 * MST>>>(
        x, d0wih_hi, d0wih_lo, nullptr, gxe, gx, VV, 4 * HD, 2, 0);
    lstm_rec_mma<<<NBLK, blk, RSMEM>>>(d0whh_hi, d0whh_lo, gx, h0, hhi, hlo, TT);

    // ---- decoder layer 1 ----
    gemm_mma<<<dim3(4 * HD / 128, (TT * BB) / 128), blk, 2 * MST>>>(
        h0, d1wih_hi, d1wih_lo, bsum_p + 8192, nullptr, gx, HD, 4 * HD, 0, 0);
    lstm_rec_mma<<<NBLK, blk, RSMEM>>>(d1whh_hi, d1whh_lo, gx, h1, hhi, hlo, TT);

    // ---- output projection (time-major -> [B,T,V]) ----
    gemm_mma<<<dim3(VV / 128, (TT * BB) / 128), blk, 2 * MST>>>(
        h1, outw_hi, outw_lo, out_b, nullptr, out, HD, VV, 0, 1);
}

// round 11
// speedup vs baseline: 3.1780x; 1.1495x over previous
#include <cuda_runtime.h>
#include <cuda_bf16.h>
#include <cstdint>

#define BB 128
#define SSEQ 16
#define TT 256
#define ZZ 512
#define HC 1024
#define EE 512
#define HD 1024
#define VV 1024
#define NBLK 128

// ---------------- scratch (device globals; zero-init at module load) ----------------
__device__ float g_zero[BB * HD];                       // never written: stays zero
__device__ float g_cin[SSEQ * BB * HC];
__device__ float g_gxc[SSEQ * BB * 4 * HC];             // perm gate order
__device__ float g_condh[SSEQ * BB * HC];
__device__ float g_emb[SSEQ * BB * EE];
__device__ float g_gxe[SSEQ * BB * 4 * HD];             // perm
__device__ float g_gx[TT * BB * 4 * HD];                // perm
__device__ float g_h0[TT * BB * HD];
__device__ float g_h1[TT * BB * HD];
__device__ float g_bsum_p[3 * 4 * HD];
// bf16 h history (hi/lo split), shared across the three recurrences (serial launches)
__device__ __align__(16) __nv_bfloat16 g_hhi[TT * BB * HD];
__device__ __align__(16) __nv_bfloat16 g_hlo[TT * BB * HD];
// bf16 hi/lo split weights (mma consumers)
__device__ __align__(16) __nv_bfloat16 g_cwih_hi[4 * HC * HC];
__device__ __align__(16) __nv_bfloat16 g_cwih_lo[4 * HC * HC];
__device__ __align__(16) __nv_bfloat16 g_cwhh_hi[4 * HC * HC];
__device__ __align__(16) __nv_bfloat16 g_cwhh_lo[4 * HC * HC];
__device__ __align__(16) __nv_bfloat16 g_d0wih_hi[4 * HD * VV];
__device__ __align__(16) __nv_bfloat16 g_d0wih_lo[4 * HD * VV];
__device__ __align__(16) __nv_bfloat16 g_d0wihE_hi[4 * HD * EE];
__device__ __align__(16) __nv_bfloat16 g_d0wihE_lo[4 * HD * EE];
__device__ __align__(16) __nv_bfloat16 g_d0whh_hi[4 * HD * HD];
__device__ __align__(16) __nv_bfloat16 g_d0whh_lo[4 * HD * HD];
__device__ __align__(16) __nv_bfloat16 g_d1wih_hi[4 * HD * HD];
__device__ __align__(16) __nv_bfloat16 g_d1wih_lo[4 * HD * HD];
__device__ __align__(16) __nv_bfloat16 g_d1whh_hi[4 * HD * HD];
__device__ __align__(16) __nv_bfloat16 g_d1whh_lo[4 * HD * HD];
__device__ __align__(16) __nv_bfloat16 g_outw_hi[VV * HD];
__device__ __align__(16) __nv_bfloat16 g_outw_lo[VV * HD];

// grid-barrier state
__device__ volatile unsigned int g_bar_gen;
__device__ unsigned int g_bar_cnt;

// ---------------- helpers ----------------
__device__ __forceinline__ unsigned long long ffma2(unsigned long long a,
                                                    unsigned long long b,
                                                    unsigned long long c) {
    unsigned long long d;
    asm("fma.rn.f32x2 %0, %1, %2, %3;" : "=l"(d) : "l"(a), "l"(b), "l"(c));
    return d;
}
__device__ __forceinline__ unsigned long long pk2(float x, float y) {
    unsigned long long r;
    asm("mov.b64 %0, {%1, %2};" : "=l"(r) : "f"(x), "f"(y));
    return r;
}
__device__ __forceinline__ float2 upk2(unsigned long long v) {
    float2 d;
    asm("mov.b64 {%0, %1}, %2;" : "=f"(d.x), "=f"(d.y) : "l"(v));
    return d;
}
__device__ __forceinline__ float4 ldcg4(const float* p) {
    return __ldcg((const float4*)(p));
}
__device__ __forceinline__ float sigm(float x) { return 1.f / (1.f + expf(-x)); }

__device__ __forceinline__ uint32_t smem_u32(const void* p) {
    uint32_t a;
    asm("{ .reg .u64 t; cvta.to.shared.u64 t, %1; cvt.u32.u64 %0, t; }" : "=r"(a) : "l"(p));
    return a;
}
__device__ __forceinline__ uint32_t pack_bf16(__nv_bfloat16 a, __nv_bfloat16 b) {
    return (uint32_t)__bfloat16_as_ushort(a) | ((uint32_t)__bfloat16_as_ushort(b) << 16);
}
__device__ __forceinline__ void split2(float x, float y, uint32_t& hp, uint32_t& lp) {
    __nv_bfloat16 hx = __float2bfloat16(x), hy = __float2bfloat16(y);
    __nv_bfloat16 lx = __float2bfloat16(x - __bfloat162float(hx));
    __nv_bfloat16 ly = __float2bfloat16(y - __bfloat162float(hy));
    hp = pack_bf16(hx, hy);
    lp = pack_bf16(lx, ly);
}

// ---------------- mma.sync (HMMA) + cp.async primitives — baseline PTX ----------------
#define MMA_BF16(d, a, b0, b1)                                                  \
    asm volatile("mma.sync.aligned.m16n8k16.row.col.f32.bf16.bf16.f32 "         \
        "{%0,%1,%2,%3}, {%4,%5,%6,%7}, {%8,%9}, {%0,%1,%2,%3};"                 \
        : "+f"((d)[0]), "+f"((d)[1]), "+f"((d)[2]), "+f"((d)[3])                \
        : "r"((a)[0]), "r"((a)[1]), "r"((a)[2]), "r"((a)[3]), "r"(b0), "r"(b1))

#define LDMX4(r, addr)                                                          \
    asm volatile("ldmatrix.sync.aligned.m8n8.x4.shared.b16 {%0,%1,%2,%3}, [%4];" \
        : "=r"((r)[0]), "=r"((r)[1]), "=r"((r)[2]), "=r"((r)[3]) : "r"(addr))

#define CP_ASYNC16(dst, src) \
    asm volatile("cp.async.cg.shared.global [%0], [%1], 16;" :: "r"(dst), "l"(src))
#define CP_COMMIT() asm volatile("cp.async.commit_group;" ::: "memory")
#define CP_WAIT(n)  asm volatile("cp.async.wait_group %0;" :: "n"(n) : "memory")

// ---------------- HMMA GEMM: C[M,N] = gather(A)[M,K] * W[N,K]^T (+bias)(+Cin) ----------------
// 128x128 tile per CTA, 8 warps (2 m x 4 n), warp tile 64x32, K-chunk 32.
// A fp32 split to bf16 hi/lo in transit; W pre-split. 3 mmas per (frag,k16): hh, hl, lh.
// Rows of 64B (32 bf16); 16B-chunk XOR swizzle: phys_chunk = logical ^ (row & 3).
// amode: 0 = A row m; 2 = prev-x gather (m=t*BB+b reads x row b*TT+t-1; zeros at t==0).
// Cin (if set): row (t>>4)*BB+b (embedding addend).  cmode: 0 = row m; 1 = row (b*TT+t).
#define MST 32768
__global__ __launch_bounds__(256, 1)
void gemm_mma(const float* __restrict__ A,
              const __nv_bfloat16* __restrict__ Whi,
              const __nv_bfloat16* __restrict__ Wlo,
              const float* __restrict__ bias, const float* __restrict__ Cin,
              float* __restrict__ C,
              int K, int N, int amode, int cmode)
{
    extern __shared__ char sm[];
    const uint32_t sb = smem_u32(sm);
    const int tid = threadIdx.x;
    const int lane = tid & 31;
    const int wid = tid >> 5;
    const int warp_m = wid & 1;
    const int warp_n = wid >> 1;
    const int m0 = blockIdx.y << 7;
    const int n0 = blockIdx.x << 7;

    const int lrow = tid >> 1;
    const int half = tid & 1;

    const float* arow;
    {
        int m = m0 + lrow;
        if (amode == 0) {
            arow = A + (size_t)m * K;
        } else {
            int t = m >> 7, b = m & 127;
            arow = (t == 0) ? g_zero : A + ((size_t)b * TT + (t - 1)) * 1024;
        }
    }
    const uint4* whrow = (const uint4*)(Whi + (size_t)(n0 + lrow) * K);
    const uint4* wlrow = (const uint4*)(Wlo + (size_t)(n0 + lrow) * K);

    const uint32_t sst0 = (uint32_t)lrow * 64u + (uint32_t)(((half * 2)     ^ (lrow & 3)) << 4);
    const uint32_t sst1 = (uint32_t)lrow * 64u + (uint32_t)(((half * 2 + 1) ^ (lrow & 3)) << 4);

    uint32_t a_addr[4][2], b_addr[2][2];
    {
        int ar = warp_m * 64 + (lane & 7) + (((lane >> 3) & 1) << 3);
        int akh = lane >> 4;
        int br = warp_n * 32 + (lane & 7) + ((lane >> 4) << 3);
        int bkh = (lane >> 3) & 1;
#pragma unroll
        for (int mi = 0; mi < 4; ++mi)
#pragma unroll
            for (int kk = 0; kk < 2; ++kk) {
                int row = ar + mi * 16;
                a_addr[mi][kk] = sb + (uint32_t)row * 64u
                               + (uint32_t)((((kk << 1) | akh) ^ (row & 3)) << 4);
            }
#pragma unroll
        for (int ng = 0; ng < 2; ++ng)
#pragma unroll
            for (int kk = 0; kk < 2; ++kk) {
                int row = br + ng * 16;
                b_addr[ng][kk] = sb + 16384u + (uint32_t)row * 64u
                               + (uint32_t)((((kk << 1) | bkh) ^ (row & 3)) << 4);
            }
    }

    float acc[4][4][4];
#pragma unroll
    for (int mi = 0; mi < 4; ++mi)
#pragma unroll
        for (int nf = 0; nf < 4; ++nf)
#pragma unroll
            for (int q = 0; q < 4; ++q) acc[mi][nf][q] = 0.f;

    const int NC = K >> 5;
    float4 pa[4];
    uint4 pwh[2], pwl[2];

#pragma unroll
    for (int i = 0; i < 4; ++i) pa[i] = ldcg4(arow + half * 16 + i * 4);
#pragma unroll
    for (int j = 0; j < 2; ++j) {
        pwh[j] = __ldcg(whrow + half * 2 + j);
        pwl[j] = __ldcg(wlrow + half * 2 + j);
    }
    {
        uint32_t h0a, l0a, h0b, l0b, h1a, l1a, h1b, l1b;
        split2(pa[0].x, pa[0].y, h0a, l0a); split2(pa[0].z, pa[0].w, h0b, l0b);
        split2(pa[1].x, pa[1].y, h1a, l1a); split2(pa[1].z, pa[1].w, h1b, l1b);
        *(uint4*)(sm + sst0)         = make_uint4(h0a, h0b, h1a, h1b);
        *(uint4*)(sm + 8192 + sst0)  = make_uint4(l0a, l0b, l1a, l1b);
        split2(pa[2].x, pa[2].y, h0a, l0a); split2(pa[2].z, pa[2].w, h0b, l0b);
        split2(pa[3].x, pa[3].y, h1a, l1a); split2(pa[3].z, pa[3].w, h1b, l1b);
        *(uint4*)(sm + sst1)         = make_uint4(h0a, h0b, h1a, h1b);
        *(uint4*)(sm + 8192 + sst1)  = make_uint4(l0a, l0b, l1a, l1b);
        *(uint4*)(sm + 16384 + sst0) = pwh[0];
        *(uint4*)(sm + 16384 + sst1) = pwh[1];
        *(uint4*)(sm + 24576 + sst0) = pwl[0];
        *(uint4*)(sm + 24576 + sst1) = pwl[1];
    }
    __syncthreads();

    for (int c = 0; c < NC; ++c) {
        const int cur = c & 1;
        const uint32_t soff = (uint32_t)cur * MST;
        if (c + 1 < NC) {
#pragma unroll
            for (int i = 0; i < 4; ++i)
                pa[i] = ldcg4(arow + (c + 1) * 32 + half * 16 + i * 4);
#pragma unroll
            for (int j = 0; j < 2; ++j) {
                pwh[j] = __ldcg(whrow + (c + 1) * 4 + half * 2 + j);
                pwl[j] = __ldcg(wlrow + (c + 1) * 4 + half * 2 + j);
            }
        }

#pragma unroll
        for (int kk = 0; kk < 2; ++kk) {
            uint32_t ah[4][4], al[4][4], bh[2][4], bl[2][4];
#pragma unroll
            for (int mi = 0; mi < 4; ++mi) {
                LDMX4(ah[mi], a_addr[mi][kk] + soff);
                LDMX4(al[mi], a_addr[mi][kk] + soff + 8192u);
            }
#pragma unroll
            for (int ng = 0; ng < 2; ++ng) {
                LDMX4(bh[ng], b_addr[ng][kk] + soff);
                LDMX4(bl[ng], b_addr[ng][kk] + soff + 8192u);
            }
#pragma unroll
            for (int mi = 0; mi < 4; ++mi) {
#pragma unroll
                for (int nf = 0; nf < 4; ++nf) {
                    const int ng = nf >> 1;
                    const int p = (nf & 1) << 1;
                    MMA_BF16(acc[mi][nf], ah[mi], bh[ng][p], bh[ng][p + 1]);
                    MMA_BF16(acc[mi][nf], ah[mi], bl[ng][p], bl[ng][p + 1]);
                    MMA_BF16(acc[mi][nf], al[mi], bh[ng][p], bh[ng][p + 1]);
                }
            }
        }

        if (c + 1 < NC) {
            char* d = sm + (cur ^ 1) * MST;
            uint32_t h0a, l0a, h0b, l0b, h1a, l1a, h1b, l1b;
            split2(pa[0].x, pa[0].y, h0a, l0a); split2(pa[0].z, pa[0].w, h0b, l0b);
            split2(pa[1].x, pa[1].y, h1a, l1a); split2(pa[1].z, pa[1].w, h1b, l1b);
            *(uint4*)(d + sst0)         = make_uint4(h0a, h0b, h1a, h1b);
            *(uint4*)(d + 8192 + sst0)  = make_uint4(l0a, l0b, l1a, l1b);
            split2(pa[2].x, pa[2].y, h0a, l0a); split2(pa[2].z, pa[2].w, h0b, l0b);
            split2(pa[3].x, pa[3].y, h1a, l1a); split2(pa[3].z, pa[3].w, h1b, l1b);
            *(uint4*)(d + sst1)         = make_uint4(h0a, h0b, h1a, h1b);
            *(uint4*)(d + 8192 + sst1)  = make_uint4(l0a, l0b, l1a, l1b);
            *(uint4*)(d + 16384 + sst0) = pwh[0];
            *(uint4*)(d + 16384 + sst1) = pwh[1];
            *(uint4*)(d + 24576 + sst0) = pwl[0];
            *(uint4*)(d + 24576 + sst1) = pwl[1];
        }
        __syncthreads();
    }

    const int grp = lane >> 2;
    const int cl  = (lane & 3) << 1;
#pragma unroll
    for (int mi = 0; mi < 4; ++mi) {
#pragma unroll
        for (int h = 0; h < 2; ++h) {
            const int row = m0 + warp_m * 64 + mi * 16 + grp + h * 8;
            size_t coff;
            if (cmode == 0) {
                coff = (size_t)row * N;
            } else {
                int t = row >> 7, b = row & 127;
                coff = ((size_t)b * TT + t) * N;
            }
            size_t cinoff = 0;
            if (Cin) {
                int cr = ((row >> 11) << 7) + (row & 127);
                cinoff = (size_t)cr * N;
            }
#pragma unroll
            for (int nf = 0; nf < 4; ++nf) {
                const int col = n0 + warp_n * 32 + nf * 8 + cl;
                float2 v = make_float2(acc[mi][nf][h * 2], acc[mi][nf][h * 2 + 1]);
                if (bias) { v.x += bias[col]; v.y += bias[col + 1]; }
                if (Cin)  {
                    float2 ci = *(const float2*)(Cin + cinoff + col);
                    v.x += ci.x; v.y += ci.y;
                }
                *(float2*)(C + coff + col) = v;
            }
        }
    }
}

// ---------------- grid barrier (all NBLK blocks co-resident) ----------------
__device__ __forceinline__ void grid_barrier()
{
    __syncthreads();
    __threadfence();
    if (threadIdx.x == 0) {
        unsigned int gen = g_bar_gen;
        if (atomicAdd(&g_bar_cnt, 1u) == NBLK - 1u) {
            g_bar_cnt = 0u;
            __threadfence();
            g_bar_gen = gen + 1u;
        } else {
            while (g_bar_gen == gen) { __nanosleep(64); }
        }
    }
    __syncthreads();
}

// ---------------- persistent HMMA LSTM recurrence (cp.async 4-stage pipeline) ----------------
// 128 CTAs: tile 64 rows (m0 = (bx>>6)*64) x 64 perm-cols (n0 = (bx&63)*64), K=1024.
// h kept as bf16 hi/lo pairs; W_hh pre-split. Stage (16KB): [Ahi 4K][Alo 4K][Whi 4K][Wlo 4K];
// 4 stages, cp.async.cg global->smem, 3 chunks in flight; gates 64x72 fp32 after stages.
#define RST 16384
#define RSMEM (4 * RST + 64 * 72 * 4)
__global__ __launch_bounds__(256, 1)
void lstm_rec_mma(const __nv_bfloat16* __restrict__ Whi,
                  const __nv_bfloat16* __restrict__ Wlo,
                  const float* __restrict__ gx,
                  float* __restrict__ hf,
                  __nv_bfloat16* __restrict__ hhi,
                  __nv_bfloat16* __restrict__ hlo,
                  int T)
{
    extern __shared__ char sm[];
    const uint32_t sb = smem_u32(sm);
    float* gsm = (float*)(sm + 4 * RST);
    const int tid = threadIdx.x;
    const int lane = tid & 31;
    const int wid = tid >> 5;
    const int warp_m = wid & 1;
    const int warp_n = wid >> 1;
    const int bx = blockIdx.x;
    const int m0 = (bx >> 6) << 6;          // 0 or 64
    const int n0 = (bx & 63) << 6;          // 0..4032 (perm cols)

    // loader: thread -> (row 0..63, 16B quad 0..3); swizzle chunk ^= row&3
    const int lrow = tid >> 2;
    const int quad = tid & 3;
    const uint32_t sst = (uint32_t)lrow * 64u + (uint32_t)((quad ^ (lrow & 3)) << 4);

    const char* whg = (const char*)(Whi + (size_t)(n0 + lrow) * 1024) + quad * 16;
    const char* wlg = (const char*)(Wlo + (size_t)(n0 + lrow) * 1024) + quad * 16;

    // ldmatrix addresses (stage 0; +soff per chunk). A: base 0 (hi) / 4096 (lo).
    // B(W): base 8192 (hi) / 12288 (lo).
    uint32_t a_addr[2][2], b_addr[2];
    {
        int ar = warp_m * 32 + (lane & 7) + (((lane >> 3) & 1) << 3);
        int akh = lane >> 4;
#pragma unroll
        for (int mi = 0; mi < 2; ++mi)
#pragma unroll
            for (int kk = 0; kk < 2; ++kk) {
                int row = ar + mi * 16;
                a_addr[mi][kk] = sb + (uint32_t)row * 64u
                               + (uint32_t)((((kk << 1) | akh) ^ (row & 3)) << 4);
            }
        int br = warp_n * 16 + (lane & 7) + ((lane >> 4) << 3);
        int bkh = (lane >> 3) & 1;
#pragma unroll
        for (int kk = 0; kk < 2; ++kk)
            b_addr[kk] = sb + 8192u + (uint32_t)br * 64u
                       + (uint32_t)((((kk << 1) | bkh) ^ (br & 3)) << 4);
    }

    const int grp = lane >> 2;
    const int cl  = (lane & 3) << 1;

    float cstate[4] = {0.f, 0.f, 0.f, 0.f};

    for (int t = 0; t < T; ++t) {
        // prefetch gx[t] for the cell (latency hidden under the GEMM)
        const float* gxt = gx + (size_t)t * BB * 4096;
        float4 gvr[4];
#pragma unroll
        for (int it = 0; it < 4; ++it) {
            const int idx = it * 256 + tid;
            gvr[it] = ldcg4(gxt + (size_t)(m0 + (idx >> 4)) * 4096 + n0 + (idx & 15) * 4);
        }

        float acc[2][2][4];
#pragma unroll
        for (int mi = 0; mi < 2; ++mi)
#pragma unroll
            for (int nf = 0; nf < 2; ++nf)
#pragma unroll
                for (int q = 0; q < 4; ++q) acc[mi][nf][q] = 0.f;

        if (t > 0) {
            const char* ahg = (const char*)(hhi + (size_t)(t - 1) * BB * 1024
                                            + (size_t)(m0 + lrow) * 1024) + quad * 16;
            const char* alg = (const char*)(hlo + (size_t)(t - 1) * BB * 1024
                                            + (size_t)(m0 + lrow) * 1024) + quad * 16;

            // prologue: chunks 0..2 into stages 0..2
#pragma unroll
            for (int s = 0; s < 3; ++s) {
                const uint32_t base = sb + (uint32_t)s * RST + sst;
                CP_ASYNC16(base,          ahg + s * 64);
                CP_ASYNC16(base + 4096u,  alg + s * 64);
                CP_ASYNC16(base + 8192u,  whg + s * 64);
                CP_ASYNC16(base + 12288u, wlg + s * 64);
                CP_COMMIT();
            }

            for (int c = 0; c < 32; ++c) {
                if (c <= 29) CP_WAIT(2);
                else if (c == 30) CP_WAIT(1);
                else CP_WAIT(0);
                __syncthreads();

                if (c + 3 < 32) {
                    const int s = (c + 3) & 3;
                    const uint32_t base = sb + (uint32_t)s * RST + sst;
                    CP_ASYNC16(base,          ahg + (c + 3) * 64);
                    CP_ASYNC16(base + 4096u,  alg + (c + 3) * 64);
                    CP_ASYNC16(base + 8192u,  whg + (c + 3) * 64);
                    CP_ASYNC16(base + 12288u, wlg + (c + 3) * 64);
                    CP_COMMIT();
                }

                const uint32_t soff = (uint32_t)(c & 3) * RST;
#pragma unroll
                for (int kk = 0; kk < 2; ++kk) {
                    uint32_t ah[2][4], al[2][4], bh[4], bl[4];
                    LDMX4(ah[0], a_addr[0][kk] + soff);
                    LDMX4(ah[1], a_addr[1][kk] + soff);
                    LDMX4(al[0], a_addr[0][kk] + soff + 4096u);
                    LDMX4(al[1], a_addr[1][kk] + soff + 4096u);
                    LDMX4(bh, b_addr[kk] + soff);
                    LDMX4(bl, b_addr[kk] + soff + 4096u);
#pragma unroll
                    for (int mi = 0; mi < 2; ++mi) {
#pragma unroll
                        for (int nf = 0; nf < 2; ++nf) {
                            const int p = nf << 1;
                            MMA_BF16(acc[mi][nf], ah[mi], bh[p], bh[p + 1]);
                            MMA_BF16(acc[mi][nf], ah[mi], bl[p], bl[p + 1]);
                            MMA_BF16(acc[mi][nf], al[mi], bh[p], bh[p + 1]);
                        }
                    }
                }
            }
            __syncthreads();   // all warps done with last stage before gsm writes reuse flow
        }

        // gate fragments -> smem (64 x 72 fp32)
#pragma unroll
        for (int mi = 0; mi < 2; ++mi)
#pragma unroll
            for (int h2 = 0; h2 < 2; ++h2) {
                const int row = warp_m * 32 + mi * 16 + grp + h2 * 8;
#pragma unroll
                for (int nf = 0; nf < 2; ++nf) {
                    const int col = warp_n * 16 + nf * 8 + cl;
                    gsm[row * 72 + col]     = acc[mi][nf][h2 * 2];
                    gsm[row * 72 + col + 1] = acc[mi][nf][h2 * 2 + 1];
                }
            }
        __syncthreads();

        // fused cell: gates = gsm + gx[t] (prefetched); c in regs; write h {fp32, hi, lo}
#pragma unroll
        for (int it = 0; it < 4; ++it) {
            const int idx = it * 256 + tid;
            const int crow = idx >> 4;
            const int cj = idx & 15;
            const int rg = m0 + crow;
            const int jg = (n0 >> 2) + cj;
            float4 ga = *(const float4*)(gsm + crow * 72 + cj * 4);
            float4 gv = gvr[it];
            float gi = sigm(ga.x + gv.x);
            float gf = sigm(ga.y + gv.y);
            float gg = tanhf(ga.z + gv.z);
            float go = sigm(ga.w + gv.w);
            float cc = gf * cstate[it] + gi * gg;
            cstate[it] = cc;
            float hv = go * tanhf(cc);
            const size_t off = (size_t)t * BB * 1024 + (size_t)rg * 1024 + jg;
            hf[off] = hv;
            __nv_bfloat16 hh = __float2bfloat16(hv);
            hhi[off] = hh;
            hlo[off] = __float2bfloat16(hv - __bfloat162float(hh));
        }

        grid_barrier();
    }
}

// ---------------- FFMA2 tile macros (remaining small GEMMs) ----------------
#define PA 66
#define PW 68
#define STORE_TILE(buf)                                            \
    do {                                                           \
        Ad[buf][lk + 0][li] = pk2(a_reg.x, a_reg.x);               \
        Ad[buf][lk + 1][li] = pk2(a_reg.y, a_reg.y);               \
        Ad[buf][lk + 2][li] = pk2(a_reg.z, a_reg.z);               \
        Ad[buf][lk + 3][li] = pk2(a_reg.w, a_reg.w);               \
        Ws[buf][lk + 0][li] = w_reg.x;                             \
        Ws[buf][lk + 1][li] = w_reg.y;                             \
        Ws[buf][lk + 2][li] = w_reg.z;                             \
        Ws[buf][lk + 3][li] = w_reg.w;                             \
    } while (0)

#define COMPUTE_TILE(buf)                                                     \
    do {                                                                      \
        _Pragma("unroll")                                                     \
        for (int k = 0; k < 16; ++k) {                                        \
            ulonglong2 a01 = *(const ulonglong2*)&Ad[buf][k][(ty << 2)];      \
            ulonglong2 a23 = *(const ulonglong2*)&Ad[buf][k][(ty << 2) + 2];  \
            ulonglong2 w01 = *(const ulonglong2*)&Ws[buf][k][(tx << 2)];      \
            acc[0][0] = ffma2(a01.x, w01.x, acc[0][0]);                       \
            acc[0][1] = ffma2(a01.x, w01.y, acc[0][1]);                       \
            acc[1][0] = ffma2(a01.y, w01.x, acc[1][0]);                       \
            acc[1][1] = ffma2(a01.y, w01.y, acc[1][1]);                       \
            acc[2][0] = ffma2(a23.x, w01.x, acc[2][0]);                       \
            acc[2][1] = ffma2(a23.x, w01.y, acc[2][1]);                       \
            acc[3][0] = ffma2(a23.y, w01.x, acc[3][0]);                       \
            acc[3][1] = ffma2(a23.y, w01.y, acc[3][1]);                       \
        }                                                                     \
    } while (0)

// amode: 0 = A row m; 1 = z-gather (m=s*BB+b reads z row b*SSEQ+s)
// act: 0 = none; 1 = tanh
__global__ __launch_bounds__(256, 2)
void gemm_nt(const float* __restrict__ A, const float* __restrict__ W,
             const float* __restrict__ bias, float* __restrict__ C,
             int M, int N, int K, int ldw, int amode, int act)
{
    __shared__ unsigned long long Ad[2][16][PA];
    __shared__ float Ws[2][16][PW];

    const int tid = threadIdx.x;
    const int m0 = blockIdx.y << 6;
    const int n0 = blockIdx.x << 6;

    const int li = tid >> 2;
    const int lk = (tid & 3) << 2;
    const int ty = tid >> 4;
    const int tx = tid & 15;

    const int m = m0 + li;
    const float* arow;
    if (amode == 0) {
        arow = A + (size_t)m * K;
    } else {
        int b = m & (BB - 1), s = m >> 7;
        arow = A + ((size_t)b * SSEQ + s) * K;
    }
    arow += lk;
    const float* wrow = W + (size_t)(n0 + li) * ldw + lk;

    const int nkt = K >> 4;
    float4 a_reg = ldcg4(arow);
    float4 w_reg = ldcg4(wrow);
    STORE_TILE(0);
    __syncthreads();

    unsigned long long acc[4][2];
#pragma unroll
    for (int r = 0; r < 4; ++r) { acc[r][0] = 0ull; acc[r][1] = 0ull; }

    for (int kt = 0; kt < nkt; ++kt) {
        const int cur = kt & 1;
        if (kt + 1 < nkt) {
            a_reg = ldcg4(arow + (size_t)(kt + 1) * 16);
            w_reg = ldcg4(wrow + (size_t)(kt + 1) * 16);
        }
        COMPUTE_TILE(cur);
        if (kt + 1 < nkt) STORE_TILE(cur ^ 1);
        __syncthreads();
    }

#pragma unroll
    for (int r = 0; r < 4; ++r) {
        const int row = m0 + (ty << 2) + r;
#pragma unroll
        for (int p = 0; p < 2; ++p) {
            const int col = n0 + (tx << 2) + (p << 1);
            float2 v = upk2(acc[r][p]);
            if (bias) { v.x += bias[col]; v.y += bias[col + 1]; }
            if (act)  { v.x = tanhf(v.x); v.y = tanhf(v.y); }
            *(float2*)(C + (size_t)row * N + col) = v;
        }
    }
}

// ---------------- one-time weight convert: fp32 -> bf16 hi/lo ----------------
__global__ void convert_w(const float* __restrict__ in,
                          __nv_bfloat16* __restrict__ hi, __nv_bfloat16* __restrict__ lo,
                          int ldk, int K, int doperm, int k0)
{
    int ro = blockIdx.x;
    int sr = doperm ? ((ro & 3) * 1024 + (ro >> 2)) : ro;
    const float* s = in + (size_t)sr * ldk + k0;
    for (int k = threadIdx.x * 4; k < K; k += blockDim.x * 4) {
        float4 v = __ldcg((const float4*)(s + k));
        uint32_t hp0, lp0, hp1, lp1;
        split2(v.x, v.y, hp0, lp0);
        split2(v.z, v.w, hp1, lp1);
        *(uint2*)(hi + (size_t)ro * K + k) = make_uint2(hp0, hp1);
        *(uint2*)(lo + (size_t)ro * K + k) = make_uint2(lp0, lp1);
    }
}

__global__ void addperm(const float* __restrict__ a, const float* __restrict__ b,
                        float* __restrict__ o)
{
    int i = blockIdx.x * blockDim.x + threadIdx.x;
    int j = i >> 2, g = i & 3;
    int s = g * 1024 + j;
    o[i] = a[s] + b[s];
}

// ---------------- host ----------------
extern "C" void kernel_launch(void* const* d_in, const int* in_sizes, int n_in,
                              void* d_out, int out_size)
{
    const float* z      = (const float*)d_in[0];
    const float* x      = (const float*)d_in[1];
    const float* fcz_w  = (const float*)d_in[2];
    const float* fcz_b  = (const float*)d_in[3];
    const float* c_wih  = (const float*)d_in[4];
    const float* c_whh  = (const float*)d_in[5];
    const float* c_bih  = (const float*)d_in[6];
    const float* c_bhh  = (const float*)d_in[7];
    const float* fcc_w  = (const float*)d_in[8];
    const float* fcc_b  = (const float*)d_in[9];
    const float* d0_wih = (const float*)d_in[10];
    const float* d0_whh = (const float*)d_in[11];
    const float* d0_bih = (const float*)d_in[12];
    const float* d0_bhh = (const float*)d_in[13];
    const float* d1_wih = (const float*)d_in[14];
    const float* d1_whh = (const float*)d_in[15];
    const float* d1_bih = (const float*)d_in[16];
    const float* d1_bhh = (const float*)d_in[17];
    const float* out_w  = (const float*)d_in[18];
    const float* out_b  = (const float*)d_in[19];
    float* out = (float*)d_out;

    float *cin, *gxc, *condh, *emb, *gxe, *gx, *h0, *h1, *bsum_p;
    __nv_bfloat16 *hhi, *hlo;
    __nv_bfloat16 *cwih_hi, *cwih_lo, *cwhh_hi, *cwhh_lo;
    __nv_bfloat16 *d0wih_hi, *d0wih_lo, *d0wihE_hi, *d0wihE_lo, *d0whh_hi, *d0whh_lo;
    __nv_bfloat16 *d1wih_hi, *d1wih_lo, *d1whh_hi, *d1whh_lo, *outw_hi, *outw_lo;
    cudaGetSymbolAddress((void**)&cin,       g_cin);
    cudaGetSymbolAddress((void**)&gxc,       g_gxc);
    cudaGetSymbolAddress((void**)&condh,     g_condh);
    cudaGetSymbolAddress((void**)&emb,       g_emb);
    cudaGetSymbolAddress((void**)&gxe,       g_gxe);
    cudaGetSymbolAddress((void**)&gx,        g_gx);
    cudaGetSymbolAddress((void**)&h0,        g_h0);
    cudaGetSymbolAddress((void**)&h1,        g_h1);
    cudaGetSymbolAddress((void**)&bsum_p,    g_bsum_p);
    cudaGetSymbolAddress((void**)&hhi,       g_hhi);
    cudaGetSymbolAddress((void**)&hlo,       g_hlo);
    cudaGetSymbolAddress((void**)&cwih_hi,   g_cwih_hi);
    cudaGetSymbolAddress((void**)&cwih_lo,   g_cwih_lo);
    cudaGetSymbolAddress((void**)&cwhh_hi,   g_cwhh_hi);
    cudaGetSymbolAddress((void**)&cwhh_lo,   g_cwhh_lo);
    cudaGetSymbolAddress((void**)&d0wih_hi,  g_d0wih_hi);
    cudaGetSymbolAddress((void**)&d0wih_lo,  g_d0wih_lo);
    cudaGetSymbolAddress((void**)&d0wihE_hi, g_d0wihE_hi);
    cudaGetSymbolAddress((void**)&d0wihE_lo, g_d0wihE_lo);
    cudaGetSymbolAddress((void**)&d0whh_hi,  g_d0whh_hi);
    cudaGetSymbolAddress((void**)&d0whh_lo,  g_d0whh_lo);
    cudaGetSymbolAddress((void**)&d1wih_hi,  g_d1wih_hi);
    cudaGetSymbolAddress((void**)&d1wih_lo,  g_d1wih_lo);
    cudaGetSymbolAddress((void**)&d1whh_hi,  g_d1whh_hi);
    cudaGetSymbolAddress((void**)&d1whh_lo,  g_d1whh_lo);
    cudaGetSymbolAddress((void**)&outw_hi,   g_outw_hi);
    cudaGetSymbolAddress((void**)&outw_lo,   g_outw_lo);

    cudaFuncSetAttribute(gemm_mma, cudaFuncAttributeMaxDynamicSharedMemorySize, 2 * MST);
    cudaFuncSetAttribute(lstm_rec_mma, cudaFuncAttributeMaxDynamicSharedMemorySize, RSMEM);

    dim3 blk(256);

    // one-time converts (gate-permuted where consumed in perm order)
    convert_w<<<4096, 256>>>(c_wih,  cwih_hi,  cwih_lo,  HC, HC, 1, 0);
    convert_w<<<4096, 256>>>(c_whh,  cwhh_hi,  cwhh_lo,  HC, HC, 1, 0);
    convert_w<<<4096, 256>>>(d0_wih, d0wih_hi, d0wih_lo, VV + EE, VV, 1, 0);
    convert_w<<<4096, 256>>>(d0_wih, d0wihE_hi, d0wihE_lo, VV + EE, EE, 1, VV);
    convert_w<<<4096, 256>>>(d0_whh, d0whh_hi, d0whh_lo, HD, HD, 1, 0);
    convert_w<<<4096, 256>>>(d1_wih, d1wih_hi, d1wih_lo, HD, HD, 1, 0);
    convert_w<<<4096, 256>>>(d1_whh, d1whh_hi, d1whh_lo, HD, HD, 1, 0);
    convert_w<<<1024, 256>>>(out_w,  outw_hi,  outw_lo,  HD, HD, 0, 0);
    addperm<<<16, 256>>>(c_bih,  c_bhh,  bsum_p);
    addperm<<<16, 256>>>(d0_bih, d0_bhh, bsum_p + 4096);
    addperm<<<16, 256>>>(d1_bih, d1_bhh, bsum_p + 8192);

    // ---- conductor ----
    gemm_nt<<<dim3(HC / 64, (SSEQ * BB) / 64), blk>>>(
        z, fcz_w, fcz_b, cin, SSEQ * BB, HC, ZZ, ZZ, 1, 0);
    gemm_mma<<<dim3(4 * HC / 128, (SSEQ * BB) / 128), blk, 2 * MST>>>(
        cin, cwih_hi, cwih_lo, bsum_p, nullptr, gxc, HC, 4 * HC, 0, 0);
    lstm_rec_mma<<<NBLK, blk, RSMEM>>>(cwhh_hi, cwhh_lo, gxc, condh, hhi, hlo, SSEQ);
    gemm_nt<<<dim3(EE / 64, (SSEQ * BB) / 64), blk>>>(
        condh, fcc_w, fcc_b, emb, SSEQ * BB, EE, HC, HC, 0, 1);
    gemm_mma<<<dim3(4 * HD / 128, (SSEQ * BB) / 128), blk, 2 * MST>>>(
        emb, d0wihE_hi, d0wihE_lo, bsum_p + 4096, nullptr, gxe, EE, 4 * HD, 0, 0);

    // ---- decoder layer 0 ----
    gemm_mma<<<dim3(4 * HD / 128, (TT * BB) / 128), blk, 2 * MST>>>(
        x, d0wih_hi, d0wih_lo, nullptr, gxe, gx, VV, 4 * HD, 2, 0);
    lstm_rec_mma<<<NBLK, blk, RSMEM>>>(d0whh_hi, d0whh_lo, gx, h0, hhi, hlo, TT);

    // ---- decoder layer 1 ----
    gemm_mma<<<dim3(4 * HD / 128, (TT * BB) / 128), blk, 2 * MST>>>(
        h0, d1wih_hi, d1wih_lo, bsum_p + 8192, nullptr, gx, HD, 4 * HD, 0, 0);
    lstm_rec_mma<<<NBLK, blk, RSMEM>>>(d1whh_hi, d1whh_lo, gx, h1, hhi, hlo, TT);

    // ---- output projection (time-major -> [B,T,V]) ----
    gemm_mma<<<dim3(VV / 128, (TT * BB) / 128), blk, 2 * MST>>>(
        h1, outw_hi, outw_lo, out_b, nullptr, out, HD, VV, 0, 1);
}